// round 4
// baseline (speedup 1.0000x reference)
#include <cuda_runtime.h>
#include <cuda_bf16.h>
#include <cstdint>

#define B_SZ 4
#define T_SZ 4096
#define DIM 512
#define E3 1536
#define HIST 128
#define M_TOT (B_SZ * T_SZ)   // 16384
#define QSCALE 0.04419417382415922f   // 1/sqrt(512)

// ---------------- device scratch (allocation-free rule) ----------------------
__device__ __align__(16) __nv_bfloat16 g_Ah[(size_t)M_TOT * DIM];
__device__ __align__(16) __nv_bfloat16 g_Al[(size_t)M_TOT * DIM];
__device__ __align__(16) __nv_bfloat16 g_Wh[(size_t)E3 * DIM];
__device__ __align__(16) __nv_bfloat16 g_Wl[(size_t)E3 * DIM];

__device__ __align__(16) __nv_bfloat16 g_qh[(size_t)M_TOT * DIM];
__device__ __align__(16) __nv_bfloat16 g_ql[(size_t)M_TOT * DIM];
__device__ __align__(16) __nv_bfloat16 g_kh[(size_t)M_TOT * DIM];
__device__ __align__(16) __nv_bfloat16 g_kl[(size_t)M_TOT * DIM];
__device__ __align__(16) __nv_bfloat16 g_vth[(size_t)B_SZ * DIM * T_SZ];
__device__ __align__(16) __nv_bfloat16 g_vtl[(size_t)B_SZ * DIM * T_SZ];

// ---------------- helpers ----------------------------------------------------
__device__ __forceinline__ void split2(float v0, float v1, uint32_t& h, uint32_t& l)
{
    __nv_bfloat16 h0 = __float2bfloat16(v0);
    __nv_bfloat16 h1 = __float2bfloat16(v1);
    __nv_bfloat16 l0 = __float2bfloat16(v0 - __bfloat162float(h0));
    __nv_bfloat16 l1 = __float2bfloat16(v1 - __bfloat162float(h1));
    h = ((uint32_t)__bfloat16_as_ushort(h1) << 16) | __bfloat16_as_ushort(h0);
    l = ((uint32_t)__bfloat16_as_ushort(l1) << 16) | __bfloat16_as_ushort(l0);
}

__device__ __forceinline__ void mma16816(float* c, const uint32_t* a, uint32_t b0, uint32_t b1)
{
    asm volatile(
        "mma.sync.aligned.m16n8k16.row.col.f32.bf16.bf16.f32 "
        "{%0,%1,%2,%3}, {%4,%5,%6,%7}, {%8,%9}, {%0,%1,%2,%3};\n"
        : "+f"(c[0]), "+f"(c[1]), "+f"(c[2]), "+f"(c[3])
        : "r"(a[0]), "r"(a[1]), "r"(a[2]), "r"(a[3]), "r"(b0), "r"(b1));
}

__device__ __forceinline__ uint32_t sptr(const void* p)
{
    return (uint32_t)__cvta_generic_to_shared(p);
}

__device__ __forceinline__ void ldsm4(uint32_t* r, uint32_t addr)
{
    asm volatile("ldmatrix.sync.aligned.m8n8.x4.shared.b16 {%0,%1,%2,%3}, [%4];"
        : "=r"(r[0]), "=r"(r[1]), "=r"(r[2]), "=r"(r[3]) : "r"(addr));
}

__device__ __forceinline__ void cpasync16(uint32_t dst, const void* src)
{
    asm volatile("cp.async.cg.shared.global [%0], [%1], 16;" :: "r"(dst), "l"(src));
}

// ---------------- fp32 -> (hi, lo) bf16 split --------------------------------
__global__ __launch_bounds__(256) void cvt_split(
    const float* __restrict__ src,
    __nv_bfloat16* __restrict__ hi, __nv_bfloat16* __restrict__ lo, int n4)
{
    int i = blockIdx.x * 256 + threadIdx.x;
    if (i >= n4) return;
    float4 v = ((const float4*)src)[i];
    uint32_t h0, l0, h1, l1;
    split2(v.x, v.y, h0, l0);
    split2(v.z, v.w, h1, l1);
    uint2 h = {h0, h1}, l = {l0, l1};
    ((uint2*)hi)[i] = h;
    ((uint2*)lo)[i] = l;
}

// ---------------- QKV GEMM: merged 3-product, cp.async x2, ldmatrix ----------
#define GBM 128
#define GBN 128
#define GBK 32
#define APITCH 40                         // bf16; 80B rows (16B-aligned, LDSM conflict-free)
#define MAT_BF (GBM * APITCH)             // 5120 bf16 per matrix
#define STAGE_BF (4 * MAT_BF)             // Ah, Al, Bh, Bl
#define GSMEM_BYTES (2 * STAGE_BF * 2)    // 81920

__device__ __forceinline__ void gemm_load_stage(
    __nv_bfloat16* stage, const __nv_bfloat16* Ah, const __nv_bfloat16* Al,
    const __nv_bfloat16* Bh, const __nv_bfloat16* Bl, int k0, int tid)
{
    const __nv_bfloat16* srcs[4] = {Ah, Al, Bh, Bl};
#pragma unroll
    for (int m = 0; m < 4; m++) {
        __nv_bfloat16* mb = stage + m * MAT_BF;
        const __nv_bfloat16* gb = srcs[m];
#pragma unroll
        for (int j = 0; j < 2; j++) {
            const int q = tid * 2 + j;        // 0..511
            const int r = q >> 2;             // row 0..127
            const int c = (q & 3) * 8;        // bf16 col 0,8,16,24
            cpasync16(sptr(mb + r * APITCH + c), gb + (size_t)r * DIM + k0 + c);
        }
    }
}

__global__ __launch_bounds__(256) void qkv_mma(const float* __restrict__ bias)
{
    extern __shared__ __align__(16) __nv_bfloat16 gsm[];

    const int tid  = threadIdx.x;
    const int warp = tid >> 5, lane = tid & 31;
    const int wm = (warp >> 1) * 32;     // 4 warps along M
    const int wn = (warp & 1) * 64;      // 2 warps along N
    const int g  = lane >> 2, tig = lane & 3;

    const int bm = blockIdx.y * GBM;
    const int bn = blockIdx.x * GBN;

    const __nv_bfloat16* Ah = g_Ah + (size_t)bm * DIM;
    const __nv_bfloat16* Al = g_Al + (size_t)bm * DIM;
    const __nv_bfloat16* Bh = g_Wh + (size_t)bn * DIM;
    const __nv_bfloat16* Bl = g_Wl + (size_t)bn * DIM;

    float acc[2][8][4] = {};

    // ldmatrix lane addressing (bf16-element offsets within a matrix tile)
    const int arow = (lane & 15);
    const int acol = (lane >> 4) << 3;               // 0 or 8
    const int brow = ((lane >> 4) << 3) + (lane & 7); // 0..15
    const int bcol = ((lane >> 3) & 1) << 3;          // 0 or 8

    gemm_load_stage(gsm, Ah, Al, Bh, Bl, 0, tid);
    asm volatile("cp.async.commit_group;");

    const int NCH = DIM / GBK;   // 16
    for (int ch = 0; ch < NCH; ch++) {
        __nv_bfloat16* stg = gsm + (ch & 1) * STAGE_BF;
        if (ch + 1 < NCH) {
            gemm_load_stage(gsm + ((ch + 1) & 1) * STAGE_BF, Ah, Al, Bh, Bl,
                            (ch + 1) * GBK, tid);
            asm volatile("cp.async.commit_group;");
            asm volatile("cp.async.wait_group 1;");
        } else {
            asm volatile("cp.async.wait_group 0;");
        }
        __syncthreads();

        __nv_bfloat16* sAh = stg;
        __nv_bfloat16* sAl = stg + MAT_BF;
        __nv_bfloat16* sBh = stg + 2 * MAT_BF;
        __nv_bfloat16* sBl = stg + 3 * MAT_BF;

#pragma unroll
        for (int ks = 0; ks < 2; ks++) {
            const int k = ks * 16;
            uint32_t ah[2][4], al[2][4];
#pragma unroll
            for (int mi = 0; mi < 2; mi++) {
                const int r = wm + mi * 16 + arow;
                ldsm4(ah[mi], sptr(sAh + r * APITCH + k + acol));
                ldsm4(al[mi], sptr(sAl + r * APITCH + k + acol));
            }
#pragma unroll
            for (int np = 0; np < 4; np++) {
                const int n0 = wn + np * 16 + brow;
                uint32_t bh[4], bl[4];
                ldsm4(bh, sptr(sBh + n0 * APITCH + k + bcol));
                ldsm4(bl, sptr(sBl + n0 * APITCH + k + bcol));
#pragma unroll
                for (int mi = 0; mi < 2; mi++) {
                    float* c0 = acc[mi][2 * np];
                    float* c1 = acc[mi][2 * np + 1];
                    mma16816(c0, ah[mi], bh[0], bh[1]);
                    mma16816(c0, ah[mi], bl[0], bl[1]);
                    mma16816(c0, al[mi], bh[0], bh[1]);
                    mma16816(c1, ah[mi], bh[2], bh[3]);
                    mma16816(c1, ah[mi], bl[2], bl[3]);
                    mma16816(c1, al[mi], bh[2], bh[3]);
                }
            }
        }
        __syncthreads();
    }

    // epilogue: bias, then route to q (scaled) / k / v-transposed split stores
    const int sec = bn >> 9;            // 0=q, 1=k, 2=v
#pragma unroll
    for (int mi = 0; mi < 2; mi++) {
#pragma unroll
        for (int ni = 0; ni < 8; ni++) {
            const int m0 = bm + wm + mi * 16 + g;
            const int cc = bn + wn + ni * 8 + tig * 2;
            const int lc = cc & 511;
            const float bb0 = bias[cc], bb1 = bias[cc + 1];
            float v00 = acc[mi][ni][0] + bb0, v01 = acc[mi][ni][1] + bb1;
            float v10 = acc[mi][ni][2] + bb0, v11 = acc[mi][ni][3] + bb1;
            if (sec == 0) { v00 *= QSCALE; v01 *= QSCALE; v10 *= QSCALE; v11 *= QSCALE; }
            uint32_t h0, l0, h1, l1;
            split2(v00, v01, h0, l0);
            split2(v10, v11, h1, l1);
            if (sec == 0) {
                *(uint32_t*)&g_qh[(size_t)m0 * DIM + lc]       = h0;
                *(uint32_t*)&g_ql[(size_t)m0 * DIM + lc]       = l0;
                *(uint32_t*)&g_qh[(size_t)(m0 + 8) * DIM + lc] = h1;
                *(uint32_t*)&g_ql[(size_t)(m0 + 8) * DIM + lc] = l1;
            } else if (sec == 1) {
                *(uint32_t*)&g_kh[(size_t)m0 * DIM + lc]       = h0;
                *(uint32_t*)&g_kl[(size_t)m0 * DIM + lc]       = l0;
                *(uint32_t*)&g_kh[(size_t)(m0 + 8) * DIM + lc] = h1;
                *(uint32_t*)&g_kl[(size_t)(m0 + 8) * DIM + lc] = l1;
            } else {
                const int b = m0 >> 12, t = m0 & 4095;
                const size_t base = (size_t)b * DIM * T_SZ;
                g_vth[base + (size_t)lc * T_SZ + t]           = __ushort_as_bfloat16((unsigned short)(h0 & 0xFFFF));
                g_vth[base + (size_t)(lc + 1) * T_SZ + t]     = __ushort_as_bfloat16((unsigned short)(h0 >> 16));
                g_vtl[base + (size_t)lc * T_SZ + t]           = __ushort_as_bfloat16((unsigned short)(l0 & 0xFFFF));
                g_vtl[base + (size_t)(lc + 1) * T_SZ + t]     = __ushort_as_bfloat16((unsigned short)(l0 >> 16));
                g_vth[base + (size_t)lc * T_SZ + t + 8]       = __ushort_as_bfloat16((unsigned short)(h1 & 0xFFFF));
                g_vth[base + (size_t)(lc + 1) * T_SZ + t + 8] = __ushort_as_bfloat16((unsigned short)(h1 >> 16));
                g_vtl[base + (size_t)lc * T_SZ + t + 8]       = __ushort_as_bfloat16((unsigned short)(l1 & 0xFFFF));
                g_vtl[base + (size_t)(lc + 1) * T_SZ + t + 8] = __ushort_as_bfloat16((unsigned short)(l1 >> 16));
            }
        }
    }
}

// ---------------- Banded attention via mma.sync (unchanged from R3) ----------
#define QT 64
#define NK 192
#define DC 64
#define KP 72
#define PP 200

#define AT_SMEM 124928

__global__ __launch_bounds__(256) void attn_mma(float* __restrict__ out)
{
    extern __shared__ char sm[];
    __nv_bfloat16* Qh = (__nv_bfloat16*)sm;
    __nv_bfloat16* Ql = (__nv_bfloat16*)(sm + 9216);
    __nv_bfloat16* Kh = (__nv_bfloat16*)(sm + 18432);
    __nv_bfloat16* Kl = (__nv_bfloat16*)(sm + 46080);
    float*         Ps = (float*)sm;
    __nv_bfloat16* Vth = (__nv_bfloat16*)sm;
    __nv_bfloat16* Vtl = (__nv_bfloat16*)(sm + 25600);
    __nv_bfloat16* Ph = (__nv_bfloat16*)(sm + 73728);
    __nv_bfloat16* Pl = (__nv_bfloat16*)(sm + 99328);

    const int b   = blockIdx.y;
    const int i0  = blockIdx.x * QT;
    const int tid = threadIdx.x;
    const int warp = tid >> 5, lane = tid & 31;
    const int g = lane >> 2, tig = lane & 3;
    const int jbase = i0 - HIST;

    const int wm = (warp >> 2) * 32;
    const int wn = (warp & 3) * 48;
    float acc[2][6][4] = {};

    for (int dc = 0; dc < DIM / DC; dc++) {
        const int d0 = dc * DC;
        __syncthreads();
#pragma unroll
        for (int it = 0; it < 2; it++) {
            const int idx = tid + it * 256;
            const int r = idx >> 3, c8 = (idx & 7) * 8;
            const size_t off = (size_t)(b * T_SZ + i0 + r) * DIM + d0 + c8;
            *(uint4*)&Qh[r * KP + c8] = *(const uint4*)(g_qh + off);
            *(uint4*)&Ql[r * KP + c8] = *(const uint4*)(g_ql + off);
        }
#pragma unroll
        for (int it = 0; it < 6; it++) {
            const int idx = tid + it * 256;
            const int r = idx >> 3, c8 = (idx & 7) * 8;
            const int j = jbase + r;
            const int jc = j < 0 ? 0 : j;
            const size_t off = (size_t)(b * T_SZ + jc) * DIM + d0 + c8;
            *(uint4*)&Kh[r * KP + c8] = *(const uint4*)(g_kh + off);
            *(uint4*)&Kl[r * KP + c8] = *(const uint4*)(g_kl + off);
        }
        __syncthreads();

#pragma unroll
        for (int ks = 0; ks < DC / 16; ks++) {
            const int k = ks * 16;
            uint32_t ah[2][4], al[2][4];
#pragma unroll
            for (int mi = 0; mi < 2; mi++) {
                const int r0 = wm + mi * 16 + g;
                ah[mi][0] = *(const uint32_t*)&Qh[r0 * KP + k + tig * 2];
                ah[mi][1] = *(const uint32_t*)&Qh[(r0 + 8) * KP + k + tig * 2];
                ah[mi][2] = *(const uint32_t*)&Qh[r0 * KP + k + 8 + tig * 2];
                ah[mi][3] = *(const uint32_t*)&Qh[(r0 + 8) * KP + k + 8 + tig * 2];
                al[mi][0] = *(const uint32_t*)&Ql[r0 * KP + k + tig * 2];
                al[mi][1] = *(const uint32_t*)&Ql[(r0 + 8) * KP + k + tig * 2];
                al[mi][2] = *(const uint32_t*)&Ql[r0 * KP + k + 8 + tig * 2];
                al[mi][3] = *(const uint32_t*)&Ql[(r0 + 8) * KP + k + 8 + tig * 2];
            }
#pragma unroll
            for (int ni = 0; ni < 6; ni++) {
                const int n0 = wn + ni * 8 + g;
                const uint32_t bh0 = *(const uint32_t*)&Kh[n0 * KP + k + tig * 2];
                const uint32_t bh1 = *(const uint32_t*)&Kh[n0 * KP + k + 8 + tig * 2];
                const uint32_t bl0 = *(const uint32_t*)&Kl[n0 * KP + k + tig * 2];
                const uint32_t bl1 = *(const uint32_t*)&Kl[n0 * KP + k + 8 + tig * 2];
#pragma unroll
                for (int mi = 0; mi < 2; mi++) {
                    mma16816(acc[mi][ni], ah[mi], bh0, bh1);
                    mma16816(acc[mi][ni], ah[mi], bl0, bl1);
                    mma16816(acc[mi][ni], al[mi], bh0, bh1);
                }
            }
        }
    }
    __syncthreads();

#pragma unroll
    for (int mi = 0; mi < 2; mi++) {
#pragma unroll
        for (int ni = 0; ni < 6; ni++) {
            const int m0 = wm + mi * 16 + g;
            const int n0 = wn + ni * 8 + tig * 2;
#pragma unroll
            for (int e = 0; e < 4; e++) {
                const int m = m0 + (e >> 1) * 8;
                const int n = n0 + (e & 1);
                const bool valid = (n >= m) && (n <= m + HIST) && (i0 + n >= HIST);
                Ps[m * PP + n] = valid ? acc[mi][ni][e] : -1e30f;
            }
        }
    }
    __syncthreads();

#pragma unroll
    for (int rr = 0; rr < 8; rr++) {
        const int q = warp * 8 + rr;
        float v[6];
        float mx = -1e30f;
#pragma unroll
        for (int s = 0; s < 6; s++) {
            v[s] = Ps[q * PP + lane + 32 * s];
            mx = fmaxf(mx, v[s]);
        }
#pragma unroll
        for (int off = 16; off; off >>= 1)
            mx = fmaxf(mx, __shfl_xor_sync(0xFFFFFFFFu, mx, off));
        float sum = 0.f;
#pragma unroll
        for (int s = 0; s < 6; s++) {
            v[s] = __expf(v[s] - mx);
            sum += v[s];
        }
#pragma unroll
        for (int off = 16; off; off >>= 1)
            sum += __shfl_xor_sync(0xFFFFFFFFu, sum, off);
        const float inv = 1.f / sum;
#pragma unroll
        for (int s = 0; s < 6; s++) {
            const float p = v[s] * inv;
            const __nv_bfloat16 ph = __float2bfloat16(p);
            const __nv_bfloat16 pl = __float2bfloat16(p - __bfloat162float(ph));
            Ph[q * PP + lane + 32 * s] = ph;
            Pl[q * PP + lane + 32 * s] = pl;
        }
    }

    const int wn2 = (warp & 3) * 16;
    const size_t vbase = (size_t)b * DIM * T_SZ;

    for (int dc = 0; dc < DIM / DC; dc++) {
        const int d0 = dc * DC;
        __syncthreads();
#pragma unroll
        for (int it = 0; it < 12; it++) {
            const int idx = tid + it * 256;
            const int r = idx / 48;
            const int c = (idx % 48) * 4;
            int j = jbase + c;
            if (j < 0) j = 0;
            const size_t off = vbase + (size_t)(d0 + r) * T_SZ + j;
            *(uint2*)&Vth[r * PP + c] = *(const uint2*)(g_vth + off);
            *(uint2*)&Vtl[r * PP + c] = *(const uint2*)(g_vtl + off);
        }
        __syncthreads();

        float oacc[2][2][4] = {};
#pragma unroll
        for (int ks = 0; ks < NK / 16; ks++) {
            const int k = ks * 16;
            uint32_t ph_[2][4], pl_[2][4];
#pragma unroll
            for (int mi = 0; mi < 2; mi++) {
                const int r0 = wm + mi * 16 + g;
                ph_[mi][0] = *(const uint32_t*)&Ph[r0 * PP + k + tig * 2];
                ph_[mi][1] = *(const uint32_t*)&Ph[(r0 + 8) * PP + k + tig * 2];
                ph_[mi][2] = *(const uint32_t*)&Ph[r0 * PP + k + 8 + tig * 2];
                ph_[mi][3] = *(const uint32_t*)&Ph[(r0 + 8) * PP + k + 8 + tig * 2];
                pl_[mi][0] = *(const uint32_t*)&Pl[r0 * PP + k + tig * 2];
                pl_[mi][1] = *(const uint32_t*)&Pl[(r0 + 8) * PP + k + tig * 2];
                pl_[mi][2] = *(const uint32_t*)&Pl[r0 * PP + k + 8 + tig * 2];
                pl_[mi][3] = *(const uint32_t*)&Pl[(r0 + 8) * PP + k + 8 + tig * 2];
            }
#pragma unroll
            for (int ni = 0; ni < 2; ni++) {
                const int n0 = wn2 + ni * 8 + g;
                const uint32_t vh0 = *(const uint32_t*)&Vth[n0 * PP + k + tig * 2];
                const uint32_t vh1 = *(const uint32_t*)&Vth[n0 * PP + k + 8 + tig * 2];
                const uint32_t vl0 = *(const uint32_t*)&Vtl[n0 * PP + k + tig * 2];
                const uint32_t vl1 = *(const uint32_t*)&Vtl[n0 * PP + k + 8 + tig * 2];
#pragma unroll
                for (int mi = 0; mi < 2; mi++) {
                    mma16816(oacc[mi][ni], ph_[mi], vh0, vh1);
                    mma16816(oacc[mi][ni], ph_[mi], vl0, vl1);
                    mma16816(oacc[mi][ni], pl_[mi], vh0, vh1);
                }
            }
        }

#pragma unroll
        for (int mi = 0; mi < 2; mi++) {
#pragma unroll
            for (int ni = 0; ni < 2; ni++) {
                const int m0 = wm + mi * 16 + g;
                const int col = d0 + wn2 + ni * 8 + tig * 2;
                const size_t row = (size_t)b * T_SZ + i0 + m0;
                float2 v0 = {oacc[mi][ni][0], oacc[mi][ni][1]};
                float2 v1 = {oacc[mi][ni][2], oacc[mi][ni][3]};
                *(float2*)&out[row * DIM + col]       = v0;
                *(float2*)&out[(row + 8) * DIM + col] = v1;
            }
        }
    }
}

// ---------------- launch -----------------------------------------------------
extern "C" void kernel_launch(void* const* d_in, const int* in_sizes, int n_in,
                              void* d_out, int out_size)
{
    const float* x    = (const float*)d_in[0];
    const float* Wqkv = (const float*)d_in[1];
    const float* bqkv = (const float*)d_in[2];
    float* out = (float*)d_out;

    cudaFuncSetAttribute(attn_mma,
                         cudaFuncAttributeMaxDynamicSharedMemorySize, AT_SMEM);
    cudaFuncSetAttribute(qkv_mma,
                         cudaFuncAttributeMaxDynamicSharedMemorySize, GSMEM_BYTES);

    __nv_bfloat16 *ah, *al, *wh, *wl;
    cudaGetSymbolAddress((void**)&ah, g_Ah);
    cudaGetSymbolAddress((void**)&al, g_Al);
    cudaGetSymbolAddress((void**)&wh, g_Wh);
    cudaGetSymbolAddress((void**)&wl, g_Wl);

    {
        int n4 = (M_TOT * DIM) / 4;
        cvt_split<<<(n4 + 255) / 256, 256>>>(x, ah, al, n4);
    }
    {
        int n4 = (E3 * DIM) / 4;
        cvt_split<<<(n4 + 255) / 256, 256>>>(Wqkv, wh, wl, n4);
    }

    dim3 ggrid(E3 / GBN, M_TOT / GBM);       // (12, 128)
    qkv_mma<<<ggrid, 256, GSMEM_BYTES>>>(bqkv);

    dim3 agrid(T_SZ / QT, B_SZ);             // (64, 4)
    attn_mma<<<agrid, 256, AT_SMEM>>>(out);
}

// round 5
// speedup vs baseline: 1.6538x; 1.6538x over previous
#include <cuda_runtime.h>
#include <cuda_bf16.h>
#include <cstdint>

#define B_SZ 4
#define T_SZ 4096
#define DIM 512
#define E3 1536
#define HIST 128
#define M_TOT (B_SZ * T_SZ)   // 16384
#define QSCALE 0.04419417382415922f   // 1/sqrt(512)

// ---------------- device scratch (allocation-free rule) ----------------------
__device__ __align__(16) __nv_bfloat16 g_Ah[(size_t)M_TOT * DIM];
__device__ __align__(16) __nv_bfloat16 g_Al[(size_t)M_TOT * DIM];
__device__ __align__(16) __nv_bfloat16 g_Wh[(size_t)E3 * DIM];
__device__ __align__(16) __nv_bfloat16 g_Wl[(size_t)E3 * DIM];

__device__ __align__(16) __nv_bfloat16 g_qh[(size_t)M_TOT * DIM];
__device__ __align__(16) __nv_bfloat16 g_ql[(size_t)M_TOT * DIM];
__device__ __align__(16) __nv_bfloat16 g_kh[(size_t)M_TOT * DIM];
__device__ __align__(16) __nv_bfloat16 g_kl[(size_t)M_TOT * DIM];
__device__ __align__(16) __nv_bfloat16 g_vth[(size_t)B_SZ * DIM * T_SZ];
__device__ __align__(16) __nv_bfloat16 g_vtl[(size_t)B_SZ * DIM * T_SZ];

// ---------------- helpers ----------------------------------------------------
__device__ __forceinline__ void split2(float v0, float v1, uint32_t& h, uint32_t& l)
{
    __nv_bfloat16 h0 = __float2bfloat16(v0);
    __nv_bfloat16 h1 = __float2bfloat16(v1);
    __nv_bfloat16 l0 = __float2bfloat16(v0 - __bfloat162float(h0));
    __nv_bfloat16 l1 = __float2bfloat16(v1 - __bfloat162float(h1));
    h = ((uint32_t)__bfloat16_as_ushort(h1) << 16) | __bfloat16_as_ushort(h0);
    l = ((uint32_t)__bfloat16_as_ushort(l1) << 16) | __bfloat16_as_ushort(l0);
}

__device__ __forceinline__ void mma16816(float* c, const uint32_t* a, uint32_t b0, uint32_t b1)
{
    asm volatile(
        "mma.sync.aligned.m16n8k16.row.col.f32.bf16.bf16.f32 "
        "{%0,%1,%2,%3}, {%4,%5,%6,%7}, {%8,%9}, {%0,%1,%2,%3};\n"
        : "+f"(c[0]), "+f"(c[1]), "+f"(c[2]), "+f"(c[3])
        : "r"(a[0]), "r"(a[1]), "r"(a[2]), "r"(a[3]), "r"(b0), "r"(b1));
}

__device__ __forceinline__ uint32_t sptr(const void* p)
{
    return (uint32_t)__cvta_generic_to_shared(p);
}

__device__ __forceinline__ void ldsm4(uint32_t* r, uint32_t addr)
{
    asm volatile("ldmatrix.sync.aligned.m8n8.x4.shared.b16 {%0,%1,%2,%3}, [%4];"
        : "=r"(r[0]), "=r"(r[1]), "=r"(r[2]), "=r"(r[3]) : "r"(addr));
}

__device__ __forceinline__ void cpasync16(uint32_t dst, const void* src)
{
    asm volatile("cp.async.cg.shared.global [%0], [%1], 16;" :: "r"(dst), "l"(src));
}

// ---------------- fp32 -> (hi, lo) bf16 split --------------------------------
__global__ __launch_bounds__(256) void cvt_split(
    const float* __restrict__ src,
    __nv_bfloat16* __restrict__ hi, __nv_bfloat16* __restrict__ lo, int n4)
{
    int i = blockIdx.x * 256 + threadIdx.x;
    if (i >= n4) return;
    float4 v = ((const float4*)src)[i];
    uint32_t h0, l0, h1, l1;
    split2(v.x, v.y, h0, l0);
    split2(v.z, v.w, h1, l1);
    uint2 h = {h0, h1}, l = {l0, l1};
    ((uint2*)hi)[i] = h;
    ((uint2*)lo)[i] = l;
}

// ---------------- QKV GEMM: 512 threads, 16 warps 4x4, cp.async x2, ldmatrix -
#define GBM 128
#define GBN 128
#define GBK 32
#define GTHREADS 512
#define APITCH 40                         // bf16; 80B rows (16B-aligned, LDSM conflict-free)
#define MAT_BF (GBM * APITCH)             // 5120 bf16 per matrix
#define STAGE_BF (4 * MAT_BF)             // Ah, Al, Bh, Bl
#define GSMEM_BYTES (2 * STAGE_BF * 2)    // 81920

__device__ __forceinline__ void gemm_load_stage(
    __nv_bfloat16* stage, const __nv_bfloat16* Ah, const __nv_bfloat16* Al,
    const __nv_bfloat16* Bh, const __nv_bfloat16* Bl, int k0, int tid)
{
    const __nv_bfloat16* srcs[4] = {Ah, Al, Bh, Bl};
    const int r = tid >> 2;               // row 0..127
    const int c = (tid & 3) * 8;          // bf16 col 0,8,16,24
#pragma unroll
    for (int m = 0; m < 4; m++) {
        cpasync16(sptr(stage + m * MAT_BF + r * APITCH + c),
                  srcs[m] + (size_t)r * DIM + k0 + c);
    }
}

__global__ __launch_bounds__(GTHREADS) void qkv_mma(const float* __restrict__ bias)
{
    extern __shared__ __align__(16) __nv_bfloat16 gsm[];

    const int tid  = threadIdx.x;
    const int warp = tid >> 5, lane = tid & 31;
    const int wm = (warp >> 2) * 32;     // 4 warps along M
    const int wn = (warp & 3) * 32;      // 4 warps along N
    const int g  = lane >> 2, tig = lane & 3;

    const int bm = blockIdx.y * GBM;
    const int bn = blockIdx.x * GBN;

    const __nv_bfloat16* Ah = g_Ah + (size_t)bm * DIM;
    const __nv_bfloat16* Al = g_Al + (size_t)bm * DIM;
    const __nv_bfloat16* Bh = g_Wh + (size_t)bn * DIM;
    const __nv_bfloat16* Bl = g_Wl + (size_t)bn * DIM;

    float acc[2][4][4] = {};

    // ldmatrix lane addressing (bf16-element offsets within a matrix tile)
    const int arow = (lane & 15);
    const int acol = (lane >> 4) << 3;                // 0 or 8
    const int brow = ((lane >> 4) << 3) + (lane & 7); // 0..15
    const int bcol = ((lane >> 3) & 1) << 3;          // 0 or 8

    gemm_load_stage(gsm, Ah, Al, Bh, Bl, 0, tid);
    asm volatile("cp.async.commit_group;");

    const int NCH = DIM / GBK;   // 16
    for (int ch = 0; ch < NCH; ch++) {
        __nv_bfloat16* stg = gsm + (ch & 1) * STAGE_BF;
        if (ch + 1 < NCH) {
            gemm_load_stage(gsm + ((ch + 1) & 1) * STAGE_BF, Ah, Al, Bh, Bl,
                            (ch + 1) * GBK, tid);
            asm volatile("cp.async.commit_group;");
            asm volatile("cp.async.wait_group 1;");
        } else {
            asm volatile("cp.async.wait_group 0;");
        }
        __syncthreads();

        __nv_bfloat16* sAh = stg;
        __nv_bfloat16* sAl = stg + MAT_BF;
        __nv_bfloat16* sBh = stg + 2 * MAT_BF;
        __nv_bfloat16* sBl = stg + 3 * MAT_BF;

#pragma unroll
        for (int ks = 0; ks < 2; ks++) {
            const int k = ks * 16;
            uint32_t ah[2][4], al[2][4];
#pragma unroll
            for (int mi = 0; mi < 2; mi++) {
                const int r = wm + mi * 16 + arow;
                ldsm4(ah[mi], sptr(sAh + r * APITCH + k + acol));
                ldsm4(al[mi], sptr(sAl + r * APITCH + k + acol));
            }
#pragma unroll
            for (int np = 0; np < 2; np++) {
                const int n0 = wn + np * 16 + brow;
                uint32_t bh[4], bl[4];
                ldsm4(bh, sptr(sBh + n0 * APITCH + k + bcol));
                ldsm4(bl, sptr(sBl + n0 * APITCH + k + bcol));
#pragma unroll
                for (int mi = 0; mi < 2; mi++) {
                    float* c0 = acc[mi][2 * np];
                    float* c1 = acc[mi][2 * np + 1];
                    mma16816(c0, ah[mi], bh[0], bh[1]);
                    mma16816(c0, ah[mi], bl[0], bl[1]);
                    mma16816(c0, al[mi], bh[0], bh[1]);
                    mma16816(c1, ah[mi], bh[2], bh[3]);
                    mma16816(c1, ah[mi], bl[2], bl[3]);
                    mma16816(c1, al[mi], bh[2], bh[3]);
                }
            }
        }
        __syncthreads();
    }

    // epilogue: bias, then route to q (scaled) / k / v-transposed split stores
    const int sec = bn >> 9;            // 0=q, 1=k, 2=v
#pragma unroll
    for (int mi = 0; mi < 2; mi++) {
#pragma unroll
        for (int ni = 0; ni < 4; ni++) {
            const int m0 = bm + wm + mi * 16 + g;
            const int cc = bn + wn + ni * 8 + tig * 2;
            const int lc = cc & 511;
            const float bb0 = bias[cc], bb1 = bias[cc + 1];
            float v00 = acc[mi][ni][0] + bb0, v01 = acc[mi][ni][1] + bb1;
            float v10 = acc[mi][ni][2] + bb0, v11 = acc[mi][ni][3] + bb1;
            if (sec == 0) { v00 *= QSCALE; v01 *= QSCALE; v10 *= QSCALE; v11 *= QSCALE; }
            uint32_t h0, l0, h1, l1;
            split2(v00, v01, h0, l0);
            split2(v10, v11, h1, l1);
            if (sec == 0) {
                *(uint32_t*)&g_qh[(size_t)m0 * DIM + lc]       = h0;
                *(uint32_t*)&g_ql[(size_t)m0 * DIM + lc]       = l0;
                *(uint32_t*)&g_qh[(size_t)(m0 + 8) * DIM + lc] = h1;
                *(uint32_t*)&g_ql[(size_t)(m0 + 8) * DIM + lc] = l1;
            } else if (sec == 1) {
                *(uint32_t*)&g_kh[(size_t)m0 * DIM + lc]       = h0;
                *(uint32_t*)&g_kl[(size_t)m0 * DIM + lc]       = l0;
                *(uint32_t*)&g_kh[(size_t)(m0 + 8) * DIM + lc] = h1;
                *(uint32_t*)&g_kl[(size_t)(m0 + 8) * DIM + lc] = l1;
            } else {
                const int b = m0 >> 12, t = m0 & 4095;
                const size_t base = (size_t)b * DIM * T_SZ;
                g_vth[base + (size_t)lc * T_SZ + t]           = __ushort_as_bfloat16((unsigned short)(h0 & 0xFFFF));
                g_vth[base + (size_t)(lc + 1) * T_SZ + t]     = __ushort_as_bfloat16((unsigned short)(h0 >> 16));
                g_vtl[base + (size_t)lc * T_SZ + t]           = __ushort_as_bfloat16((unsigned short)(l0 & 0xFFFF));
                g_vtl[base + (size_t)(lc + 1) * T_SZ + t]     = __ushort_as_bfloat16((unsigned short)(l0 >> 16));
                g_vth[base + (size_t)lc * T_SZ + t + 8]       = __ushort_as_bfloat16((unsigned short)(h1 & 0xFFFF));
                g_vth[base + (size_t)(lc + 1) * T_SZ + t + 8] = __ushort_as_bfloat16((unsigned short)(h1 >> 16));
                g_vtl[base + (size_t)lc * T_SZ + t + 8]       = __ushort_as_bfloat16((unsigned short)(l1 & 0xFFFF));
                g_vtl[base + (size_t)(lc + 1) * T_SZ + t + 8] = __ushort_as_bfloat16((unsigned short)(l1 >> 16));
            }
        }
    }
}

// ---------------- Banded attention via mma.sync (unchanged from R3) ----------
#define QT 64
#define NK 192
#define DC 64
#define KP 72
#define PP 200

#define AT_SMEM 124928

__global__ __launch_bounds__(256) void attn_mma(float* __restrict__ out)
{
    extern __shared__ char sm[];
    __nv_bfloat16* Qh = (__nv_bfloat16*)sm;
    __nv_bfloat16* Ql = (__nv_bfloat16*)(sm + 9216);
    __nv_bfloat16* Kh = (__nv_bfloat16*)(sm + 18432);
    __nv_bfloat16* Kl = (__nv_bfloat16*)(sm + 46080);
    float*         Ps = (float*)sm;
    __nv_bfloat16* Vth = (__nv_bfloat16*)sm;
    __nv_bfloat16* Vtl = (__nv_bfloat16*)(sm + 25600);
    __nv_bfloat16* Ph = (__nv_bfloat16*)(sm + 73728);
    __nv_bfloat16* Pl = (__nv_bfloat16*)(sm + 99328);

    const int b   = blockIdx.y;
    const int i0  = blockIdx.x * QT;
    const int tid = threadIdx.x;
    const int warp = tid >> 5, lane = tid & 31;
    const int g = lane >> 2, tig = lane & 3;
    const int jbase = i0 - HIST;

    const int wm = (warp >> 2) * 32;
    const int wn = (warp & 3) * 48;
    float acc[2][6][4] = {};

    for (int dc = 0; dc < DIM / DC; dc++) {
        const int d0 = dc * DC;
        __syncthreads();
#pragma unroll
        for (int it = 0; it < 2; it++) {
            const int idx = tid + it * 256;
            const int r = idx >> 3, c8 = (idx & 7) * 8;
            const size_t off = (size_t)(b * T_SZ + i0 + r) * DIM + d0 + c8;
            *(uint4*)&Qh[r * KP + c8] = *(const uint4*)(g_qh + off);
            *(uint4*)&Ql[r * KP + c8] = *(const uint4*)(g_ql + off);
        }
#pragma unroll
        for (int it = 0; it < 6; it++) {
            const int idx = tid + it * 256;
            const int r = idx >> 3, c8 = (idx & 7) * 8;
            const int j = jbase + r;
            const int jc = j < 0 ? 0 : j;
            const size_t off = (size_t)(b * T_SZ + jc) * DIM + d0 + c8;
            *(uint4*)&Kh[r * KP + c8] = *(const uint4*)(g_kh + off);
            *(uint4*)&Kl[r * KP + c8] = *(const uint4*)(g_kl + off);
        }
        __syncthreads();

#pragma unroll
        for (int ks = 0; ks < DC / 16; ks++) {
            const int k = ks * 16;
            uint32_t ah[2][4], al[2][4];
#pragma unroll
            for (int mi = 0; mi < 2; mi++) {
                const int r0 = wm + mi * 16 + g;
                ah[mi][0] = *(const uint32_t*)&Qh[r0 * KP + k + tig * 2];
                ah[mi][1] = *(const uint32_t*)&Qh[(r0 + 8) * KP + k + tig * 2];
                ah[mi][2] = *(const uint32_t*)&Qh[r0 * KP + k + 8 + tig * 2];
                ah[mi][3] = *(const uint32_t*)&Qh[(r0 + 8) * KP + k + 8 + tig * 2];
                al[mi][0] = *(const uint32_t*)&Ql[r0 * KP + k + tig * 2];
                al[mi][1] = *(const uint32_t*)&Ql[(r0 + 8) * KP + k + tig * 2];
                al[mi][2] = *(const uint32_t*)&Ql[r0 * KP + k + 8 + tig * 2];
                al[mi][3] = *(const uint32_t*)&Ql[(r0 + 8) * KP + k + 8 + tig * 2];
            }
#pragma unroll
            for (int ni = 0; ni < 6; ni++) {
                const int n0 = wn + ni * 8 + g;
                const uint32_t bh0 = *(const uint32_t*)&Kh[n0 * KP + k + tig * 2];
                const uint32_t bh1 = *(const uint32_t*)&Kh[n0 * KP + k + 8 + tig * 2];
                const uint32_t bl0 = *(const uint32_t*)&Kl[n0 * KP + k + tig * 2];
                const uint32_t bl1 = *(const uint32_t*)&Kl[n0 * KP + k + 8 + tig * 2];
#pragma unroll
                for (int mi = 0; mi < 2; mi++) {
                    mma16816(acc[mi][ni], ah[mi], bh0, bh1);
                    mma16816(acc[mi][ni], ah[mi], bl0, bl1);
                    mma16816(acc[mi][ni], al[mi], bh0, bh1);
                }
            }
        }
    }
    __syncthreads();

#pragma unroll
    for (int mi = 0; mi < 2; mi++) {
#pragma unroll
        for (int ni = 0; ni < 6; ni++) {
            const int m0 = wm + mi * 16 + g;
            const int n0 = wn + ni * 8 + tig * 2;
#pragma unroll
            for (int e = 0; e < 4; e++) {
                const int m = m0 + (e >> 1) * 8;
                const int n = n0 + (e & 1);
                const bool valid = (n >= m) && (n <= m + HIST) && (i0 + n >= HIST);
                Ps[m * PP + n] = valid ? acc[mi][ni][e] : -1e30f;
            }
        }
    }
    __syncthreads();

#pragma unroll
    for (int rr = 0; rr < 8; rr++) {
        const int q = warp * 8 + rr;
        float v[6];
        float mx = -1e30f;
#pragma unroll
        for (int s = 0; s < 6; s++) {
            v[s] = Ps[q * PP + lane + 32 * s];
            mx = fmaxf(mx, v[s]);
        }
#pragma unroll
        for (int off = 16; off; off >>= 1)
            mx = fmaxf(mx, __shfl_xor_sync(0xFFFFFFFFu, mx, off));
        float sum = 0.f;
#pragma unroll
        for (int s = 0; s < 6; s++) {
            v[s] = __expf(v[s] - mx);
            sum += v[s];
        }
#pragma unroll
        for (int off = 16; off; off >>= 1)
            sum += __shfl_xor_sync(0xFFFFFFFFu, sum, off);
        const float inv = 1.f / sum;
#pragma unroll
        for (int s = 0; s < 6; s++) {
            const float p = v[s] * inv;
            const __nv_bfloat16 ph = __float2bfloat16(p);
            const __nv_bfloat16 pl = __float2bfloat16(p - __bfloat162float(ph));
            Ph[q * PP + lane + 32 * s] = ph;
            Pl[q * PP + lane + 32 * s] = pl;
        }
    }

    const int wn2 = (warp & 3) * 16;
    const size_t vbase = (size_t)b * DIM * T_SZ;

    for (int dc = 0; dc < DIM / DC; dc++) {
        const int d0 = dc * DC;
        __syncthreads();
#pragma unroll
        for (int it = 0; it < 12; it++) {
            const int idx = tid + it * 256;
            const int r = idx / 48;
            const int c = (idx % 48) * 4;
            int j = jbase + c;
            if (j < 0) j = 0;
            const size_t off = vbase + (size_t)(d0 + r) * T_SZ + j;
            *(uint2*)&Vth[r * PP + c] = *(const uint2*)(g_vth + off);
            *(uint2*)&Vtl[r * PP + c] = *(const uint2*)(g_vtl + off);
        }
        __syncthreads();

        float oacc[2][2][4] = {};
#pragma unroll
        for (int ks = 0; ks < NK / 16; ks++) {
            const int k = ks * 16;
            uint32_t ph_[2][4], pl_[2][4];
#pragma unroll
            for (int mi = 0; mi < 2; mi++) {
                const int r0 = wm + mi * 16 + g;
                ph_[mi][0] = *(const uint32_t*)&Ph[r0 * PP + k + tig * 2];
                ph_[mi][1] = *(const uint32_t*)&Ph[(r0 + 8) * PP + k + tig * 2];
                ph_[mi][2] = *(const uint32_t*)&Ph[r0 * PP + k + 8 + tig * 2];
                ph_[mi][3] = *(const uint32_t*)&Ph[(r0 + 8) * PP + k + 8 + tig * 2];
                pl_[mi][0] = *(const uint32_t*)&Pl[r0 * PP + k + tig * 2];
                pl_[mi][1] = *(const uint32_t*)&Pl[(r0 + 8) * PP + k + tig * 2];
                pl_[mi][2] = *(const uint32_t*)&Pl[r0 * PP + k + 8 + tig * 2];
                pl_[mi][3] = *(const uint32_t*)&Pl[(r0 + 8) * PP + k + 8 + tig * 2];
            }
#pragma unroll
            for (int ni = 0; ni < 2; ni++) {
                const int n0 = wn2 + ni * 8 + g;
                const uint32_t vh0 = *(const uint32_t*)&Vth[n0 * PP + k + tig * 2];
                const uint32_t vh1 = *(const uint32_t*)&Vth[n0 * PP + k + 8 + tig * 2];
                const uint32_t vl0 = *(const uint32_t*)&Vtl[n0 * PP + k + tig * 2];
                const uint32_t vl1 = *(const uint32_t*)&Vtl[n0 * PP + k + 8 + tig * 2];
#pragma unroll
                for (int mi = 0; mi < 2; mi++) {
                    mma16816(oacc[mi][ni], ph_[mi], vh0, vh1);
                    mma16816(oacc[mi][ni], ph_[mi], vl0, vl1);
                    mma16816(oacc[mi][ni], pl_[mi], vh0, vh1);
                }
            }
        }

#pragma unroll
        for (int mi = 0; mi < 2; mi++) {
#pragma unroll
            for (int ni = 0; ni < 2; ni++) {
                const int m0 = wm + mi * 16 + g;
                const int col = d0 + wn2 + ni * 8 + tig * 2;
                const size_t row = (size_t)b * T_SZ + i0 + m0;
                float2 v0 = {oacc[mi][ni][0], oacc[mi][ni][1]};
                float2 v1 = {oacc[mi][ni][2], oacc[mi][ni][3]};
                *(float2*)&out[row * DIM + col]       = v0;
                *(float2*)&out[(row + 8) * DIM + col] = v1;
            }
        }
    }
}

// ---------------- launch -----------------------------------------------------
extern "C" void kernel_launch(void* const* d_in, const int* in_sizes, int n_in,
                              void* d_out, int out_size)
{
    const float* x    = (const float*)d_in[0];
    const float* Wqkv = (const float*)d_in[1];
    const float* bqkv = (const float*)d_in[2];
    float* out = (float*)d_out;

    cudaFuncSetAttribute(attn_mma,
                         cudaFuncAttributeMaxDynamicSharedMemorySize, AT_SMEM);
    cudaFuncSetAttribute(qkv_mma,
                         cudaFuncAttributeMaxDynamicSharedMemorySize, GSMEM_BYTES);

    __nv_bfloat16 *ah, *al, *wh, *wl;
    cudaGetSymbolAddress((void**)&ah, g_Ah);
    cudaGetSymbolAddress((void**)&al, g_Al);
    cudaGetSymbolAddress((void**)&wh, g_Wh);
    cudaGetSymbolAddress((void**)&wl, g_Wl);

    {
        int n4 = (M_TOT * DIM) / 4;
        cvt_split<<<(n4 + 255) / 256, 256>>>(x, ah, al, n4);
    }
    {
        int n4 = (E3 * DIM) / 4;
        cvt_split<<<(n4 + 255) / 256, 256>>>(Wqkv, wh, wl, n4);
    }

    dim3 ggrid(E3 / GBN, M_TOT / GBM);       // (12, 128)
    qkv_mma<<<ggrid, GTHREADS, GSMEM_BYTES>>>(bqkv);

    dim3 agrid(T_SZ / QT, B_SZ);             // (64, 4)
    attn_mma<<<agrid, 256, AT_SMEM>>>(out);
}

// round 6
// speedup vs baseline: 1.7909x; 1.0829x over previous
#include <cuda_runtime.h>
#include <cuda_bf16.h>
#include <cstdint>

#define B_SZ 4
#define T_SZ 4096
#define DIM 512
#define E3 1536
#define HIST 128
#define M_TOT (B_SZ * T_SZ)   // 16384
#define QSCALE 0.04419417382415922f   // 1/sqrt(512)

// ---------------- device scratch (allocation-free rule) ----------------------
__device__ __align__(16) __nv_bfloat16 g_Ah[(size_t)M_TOT * DIM];
__device__ __align__(16) __nv_bfloat16 g_Al[(size_t)M_TOT * DIM];
__device__ __align__(16) __nv_bfloat16 g_Wh[(size_t)E3 * DIM];
__device__ __align__(16) __nv_bfloat16 g_Wl[(size_t)E3 * DIM];

__device__ __align__(16) __nv_bfloat16 g_qh[(size_t)M_TOT * DIM];
__device__ __align__(16) __nv_bfloat16 g_ql[(size_t)M_TOT * DIM];
__device__ __align__(16) __nv_bfloat16 g_kh[(size_t)M_TOT * DIM];
__device__ __align__(16) __nv_bfloat16 g_kl[(size_t)M_TOT * DIM];
__device__ __align__(16) __nv_bfloat16 g_vth[(size_t)B_SZ * DIM * T_SZ];
__device__ __align__(16) __nv_bfloat16 g_vtl[(size_t)B_SZ * DIM * T_SZ];

// ---------------- helpers ----------------------------------------------------
__device__ __forceinline__ void split2(float v0, float v1, uint32_t& h, uint32_t& l)
{
    __nv_bfloat16 h0 = __float2bfloat16(v0);
    __nv_bfloat16 h1 = __float2bfloat16(v1);
    __nv_bfloat16 l0 = __float2bfloat16(v0 - __bfloat162float(h0));
    __nv_bfloat16 l1 = __float2bfloat16(v1 - __bfloat162float(h1));
    h = ((uint32_t)__bfloat16_as_ushort(h1) << 16) | __bfloat16_as_ushort(h0);
    l = ((uint32_t)__bfloat16_as_ushort(l1) << 16) | __bfloat16_as_ushort(l0);
}

__device__ __forceinline__ void mma16816(float* c, const uint32_t* a, uint32_t b0, uint32_t b1)
{
    asm volatile(
        "mma.sync.aligned.m16n8k16.row.col.f32.bf16.bf16.f32 "
        "{%0,%1,%2,%3}, {%4,%5,%6,%7}, {%8,%9}, {%0,%1,%2,%3};\n"
        : "+f"(c[0]), "+f"(c[1]), "+f"(c[2]), "+f"(c[3])
        : "r"(a[0]), "r"(a[1]), "r"(a[2]), "r"(a[3]), "r"(b0), "r"(b1));
}

__device__ __forceinline__ uint32_t sptr(const void* p)
{
    return (uint32_t)__cvta_generic_to_shared(p);
}

__device__ __forceinline__ void ldsm4(uint32_t* r, uint32_t addr)
{
    asm volatile("ldmatrix.sync.aligned.m8n8.x4.shared.b16 {%0,%1,%2,%3}, [%4];"
        : "=r"(r[0]), "=r"(r[1]), "=r"(r[2]), "=r"(r[3]) : "r"(addr));
}

__device__ __forceinline__ void cpasync16(uint32_t dst, const void* src)
{
    asm volatile("cp.async.cg.shared.global [%0], [%1], 16;" :: "r"(dst), "l"(src));
}

// ---------------- fp32 -> (hi, lo) bf16 split --------------------------------
__global__ __launch_bounds__(256) void cvt_split(
    const float* __restrict__ src,
    __nv_bfloat16* __restrict__ hi, __nv_bfloat16* __restrict__ lo, int n4)
{
    int i = blockIdx.x * 256 + threadIdx.x;
    if (i >= n4) return;
    float4 v = ((const float4*)src)[i];
    uint32_t h0, l0, h1, l1;
    split2(v.x, v.y, h0, l0);
    split2(v.z, v.w, h1, l1);
    uint2 h = {h0, h1}, l = {l0, l1};
    ((uint2*)hi)[i] = h;
    ((uint2*)lo)[i] = l;
}

// ---------------- QKV GEMM: 512 threads, GBK=64, cp.async x2, ldmatrix -------
#define GBM 128
#define GBN 128
#define GBK 64
#define GTHREADS 512
#define APITCH 72                         // bf16; 144B rows (16B-aligned, LDSM conflict-free)
#define MAT_BF (GBM * APITCH)             // 9216 bf16 per matrix
#define STAGE_BF (4 * MAT_BF)             // Ah, Al, Bh, Bl
#define GSMEM_BYTES (2 * STAGE_BF * 2)    // 147456

__device__ __forceinline__ void gemm_load_stage(
    __nv_bfloat16* stage, const __nv_bfloat16* Ah, const __nv_bfloat16* Al,
    const __nv_bfloat16* Bh, const __nv_bfloat16* Bl, int k0, int tid)
{
    const __nv_bfloat16* srcs[4] = {Ah, Al, Bh, Bl};
#pragma unroll
    for (int m = 0; m < 4; m++) {
        __nv_bfloat16* mb = stage + m * MAT_BF;
        const __nv_bfloat16* gb = srcs[m];
#pragma unroll
        for (int it = 0; it < 2; it++) {
            const int idx = tid + it * GTHREADS;   // 0..1023
            const int r = idx >> 3;                // row 0..127
            const int c = (idx & 7) * 8;           // bf16 col 0..56
            cpasync16(sptr(mb + r * APITCH + c), gb + (size_t)r * DIM + k0 + c);
        }
    }
}

__global__ __launch_bounds__(GTHREADS) void qkv_mma(const float* __restrict__ bias)
{
    extern __shared__ __align__(16) __nv_bfloat16 gsm[];

    const int tid  = threadIdx.x;
    const int warp = tid >> 5, lane = tid & 31;
    const int wm = (warp >> 2) * 32;     // 4 warps along M
    const int wn = (warp & 3) * 32;      // 4 warps along N
    const int g  = lane >> 2, tig = lane & 3;

    const int bm = blockIdx.y * GBM;
    const int bn = blockIdx.x * GBN;

    const __nv_bfloat16* Ah = g_Ah + (size_t)bm * DIM;
    const __nv_bfloat16* Al = g_Al + (size_t)bm * DIM;
    const __nv_bfloat16* Bh = g_Wh + (size_t)bn * DIM;
    const __nv_bfloat16* Bl = g_Wl + (size_t)bn * DIM;

    float acc[2][4][4] = {};

    // ldmatrix lane addressing
    const int arow = (lane & 15);
    const int acol = (lane >> 4) << 3;                // 0 or 8
    const int brow = ((lane >> 4) << 3) + (lane & 7); // 0..15
    const int bcol = ((lane >> 3) & 1) << 3;          // 0 or 8

    gemm_load_stage(gsm, Ah, Al, Bh, Bl, 0, tid);
    asm volatile("cp.async.commit_group;");

    const int NCH = DIM / GBK;   // 8
    for (int ch = 0; ch < NCH; ch++) {
        __nv_bfloat16* stg = gsm + (ch & 1) * STAGE_BF;
        if (ch + 1 < NCH) {
            gemm_load_stage(gsm + ((ch + 1) & 1) * STAGE_BF, Ah, Al, Bh, Bl,
                            (ch + 1) * GBK, tid);
            asm volatile("cp.async.commit_group;");
            asm volatile("cp.async.wait_group 1;");
        } else {
            asm volatile("cp.async.wait_group 0;");
        }
        __syncthreads();

        __nv_bfloat16* sAh = stg;
        __nv_bfloat16* sAl = stg + MAT_BF;
        __nv_bfloat16* sBh = stg + 2 * MAT_BF;
        __nv_bfloat16* sBl = stg + 3 * MAT_BF;

#pragma unroll
        for (int ks = 0; ks < GBK / 16; ks++) {
            const int k = ks * 16;
            uint32_t ah[2][4], al[2][4];
#pragma unroll
            for (int mi = 0; mi < 2; mi++) {
                const int r = wm + mi * 16 + arow;
                ldsm4(ah[mi], sptr(sAh + r * APITCH + k + acol));
                ldsm4(al[mi], sptr(sAl + r * APITCH + k + acol));
            }
#pragma unroll
            for (int np = 0; np < 2; np++) {
                const int n0 = wn + np * 16 + brow;
                uint32_t bh[4], bl[4];
                ldsm4(bh, sptr(sBh + n0 * APITCH + k + bcol));
                ldsm4(bl, sptr(sBl + n0 * APITCH + k + bcol));
#pragma unroll
                for (int mi = 0; mi < 2; mi++) {
                    float* c0 = acc[mi][2 * np];
                    float* c1 = acc[mi][2 * np + 1];
                    mma16816(c0, ah[mi], bh[0], bh[1]);
                    mma16816(c0, ah[mi], bl[0], bl[1]);
                    mma16816(c0, al[mi], bh[0], bh[1]);
                    mma16816(c1, ah[mi], bh[2], bh[3]);
                    mma16816(c1, ah[mi], bl[2], bl[3]);
                    mma16816(c1, al[mi], bh[2], bh[3]);
                }
            }
        }
        __syncthreads();
    }

    // epilogue: bias, then route to q (scaled) / k / v-transposed split stores
    const int sec = bn >> 9;            // 0=q, 1=k, 2=v
#pragma unroll
    for (int mi = 0; mi < 2; mi++) {
#pragma unroll
        for (int ni = 0; ni < 4; ni++) {
            const int m0 = bm + wm + mi * 16 + g;
            const int cc = bn + wn + ni * 8 + tig * 2;
            const int lc = cc & 511;
            const float bb0 = bias[cc], bb1 = bias[cc + 1];
            float v00 = acc[mi][ni][0] + bb0, v01 = acc[mi][ni][1] + bb1;
            float v10 = acc[mi][ni][2] + bb0, v11 = acc[mi][ni][3] + bb1;
            if (sec == 0) { v00 *= QSCALE; v01 *= QSCALE; v10 *= QSCALE; v11 *= QSCALE; }
            uint32_t h0, l0, h1, l1;
            split2(v00, v01, h0, l0);
            split2(v10, v11, h1, l1);
            if (sec == 0) {
                *(uint32_t*)&g_qh[(size_t)m0 * DIM + lc]       = h0;
                *(uint32_t*)&g_ql[(size_t)m0 * DIM + lc]       = l0;
                *(uint32_t*)&g_qh[(size_t)(m0 + 8) * DIM + lc] = h1;
                *(uint32_t*)&g_ql[(size_t)(m0 + 8) * DIM + lc] = l1;
            } else if (sec == 1) {
                *(uint32_t*)&g_kh[(size_t)m0 * DIM + lc]       = h0;
                *(uint32_t*)&g_kl[(size_t)m0 * DIM + lc]       = l0;
                *(uint32_t*)&g_kh[(size_t)(m0 + 8) * DIM + lc] = h1;
                *(uint32_t*)&g_kl[(size_t)(m0 + 8) * DIM + lc] = l1;
            } else {
                const int b = m0 >> 12, t = m0 & 4095;
                const size_t base = (size_t)b * DIM * T_SZ;
                g_vth[base + (size_t)lc * T_SZ + t]           = __ushort_as_bfloat16((unsigned short)(h0 & 0xFFFF));
                g_vth[base + (size_t)(lc + 1) * T_SZ + t]     = __ushort_as_bfloat16((unsigned short)(h0 >> 16));
                g_vtl[base + (size_t)lc * T_SZ + t]           = __ushort_as_bfloat16((unsigned short)(l0 & 0xFFFF));
                g_vtl[base + (size_t)(lc + 1) * T_SZ + t]     = __ushort_as_bfloat16((unsigned short)(l0 >> 16));
                g_vth[base + (size_t)lc * T_SZ + t + 8]       = __ushort_as_bfloat16((unsigned short)(h1 & 0xFFFF));
                g_vth[base + (size_t)(lc + 1) * T_SZ + t + 8] = __ushort_as_bfloat16((unsigned short)(h1 >> 16));
                g_vtl[base + (size_t)lc * T_SZ + t + 8]       = __ushort_as_bfloat16((unsigned short)(l1 & 0xFFFF));
                g_vtl[base + (size_t)(lc + 1) * T_SZ + t + 8] = __ushort_as_bfloat16((unsigned short)(l1 >> 16));
            }
        }
    }
}

// ---------------- Banded attention: QT=32, 2 CTAs/SM -------------------------
#define QT 32
#define NK 160
#define DC 64
#define KP 72
#define PP 168

// smem (bytes):
//  region A (union):
//    phase A: Qh@0 (4608), Ql@4608, Kh@9216 (23040), Kl@32256  -> 55296
//    phase B: Ps f32 @0 (32*168*4 = 21504)
//    phase C: Vth@0 (21504), Vtl@21504                          -> 43008
//  region B: Ph@55296 (10752), Pl@66048 (10752)                 -> total 76800
#define AT_SMEM 76800

__global__ __launch_bounds__(256, 2) void attn_mma(float* __restrict__ out)
{
    extern __shared__ char sm[];
    __nv_bfloat16* Qh = (__nv_bfloat16*)sm;
    __nv_bfloat16* Ql = (__nv_bfloat16*)(sm + 4608);
    __nv_bfloat16* Kh = (__nv_bfloat16*)(sm + 9216);
    __nv_bfloat16* Kl = (__nv_bfloat16*)(sm + 32256);
    float*         Ps = (float*)sm;
    __nv_bfloat16* Vth = (__nv_bfloat16*)sm;
    __nv_bfloat16* Vtl = (__nv_bfloat16*)(sm + 21504);
    __nv_bfloat16* Ph = (__nv_bfloat16*)(sm + 55296);
    __nv_bfloat16* Pl = (__nv_bfloat16*)(sm + 66048);

    const int b   = blockIdx.y;
    const int i0  = blockIdx.x * QT;
    const int tid = threadIdx.x;
    const int warp = tid >> 5, lane = tid & 31;
    const int g = lane >> 2, tig = lane & 3;
    const int jbase = i0 - HIST;

    // ---------------- phase A: S = Q K^T -------------------------------------
    const int wm = (warp >> 2) * 16;       // 2 warp-groups along M (32)
    const int wn = (warp & 3) * 40;        // 4 warp-groups along N (160)
    float acc[5][4] = {};

    for (int dc = 0; dc < DIM / DC; dc++) {
        const int d0 = dc * DC;
        __syncthreads();
        // Q tile: 32 x 64, one uint4 per thread per array
        {
            const int r = tid >> 3, c8 = (tid & 7) * 8;
            const size_t off = (size_t)(b * T_SZ + i0 + r) * DIM + d0 + c8;
            *(uint4*)&Qh[r * KP + c8] = *(const uint4*)(g_qh + off);
            *(uint4*)&Ql[r * KP + c8] = *(const uint4*)(g_ql + off);
        }
        // K tile: 160 x 64
#pragma unroll
        for (int it = 0; it < 5; it++) {
            const int idx = tid + it * 256;
            const int r = idx >> 3, c8 = (idx & 7) * 8;
            const int j = jbase + r;
            const int jc = j < 0 ? 0 : j;
            const size_t off = (size_t)(b * T_SZ + jc) * DIM + d0 + c8;
            *(uint4*)&Kh[r * KP + c8] = *(const uint4*)(g_kh + off);
            *(uint4*)&Kl[r * KP + c8] = *(const uint4*)(g_kl + off);
        }
        __syncthreads();

#pragma unroll
        for (int ks = 0; ks < DC / 16; ks++) {
            const int k = ks * 16;
            uint32_t ah[4], al[4];
            {
                const int r0 = wm + g;
                ah[0] = *(const uint32_t*)&Qh[r0 * KP + k + tig * 2];
                ah[1] = *(const uint32_t*)&Qh[(r0 + 8) * KP + k + tig * 2];
                ah[2] = *(const uint32_t*)&Qh[r0 * KP + k + 8 + tig * 2];
                ah[3] = *(const uint32_t*)&Qh[(r0 + 8) * KP + k + 8 + tig * 2];
                al[0] = *(const uint32_t*)&Ql[r0 * KP + k + tig * 2];
                al[1] = *(const uint32_t*)&Ql[(r0 + 8) * KP + k + tig * 2];
                al[2] = *(const uint32_t*)&Ql[r0 * KP + k + 8 + tig * 2];
                al[3] = *(const uint32_t*)&Ql[(r0 + 8) * KP + k + 8 + tig * 2];
            }
#pragma unroll
            for (int ni = 0; ni < 5; ni++) {
                const int n0 = wn + ni * 8 + g;
                const uint32_t bh0 = *(const uint32_t*)&Kh[n0 * KP + k + tig * 2];
                const uint32_t bh1 = *(const uint32_t*)&Kh[n0 * KP + k + 8 + tig * 2];
                const uint32_t bl0 = *(const uint32_t*)&Kl[n0 * KP + k + tig * 2];
                const uint32_t bl1 = *(const uint32_t*)&Kl[n0 * KP + k + 8 + tig * 2];
                mma16816(acc[ni], ah, bh0, bh1);
                mma16816(acc[ni], ah, bl0, bl1);
                mma16816(acc[ni], al, bh0, bh1);
            }
        }
    }
    __syncthreads();

    // masked store of S to Ps: valid iff q <= n <= q+128 and jbase+n >= 0
#pragma unroll
    for (int ni = 0; ni < 5; ni++) {
        const int m0 = wm + g;
        const int n0 = wn + ni * 8 + tig * 2;
#pragma unroll
        for (int e = 0; e < 4; e++) {
            const int m = m0 + (e >> 1) * 8;
            const int n = n0 + (e & 1);
            const bool valid = (n >= m) && (n <= m + HIST) && (jbase + n >= 0);
            Ps[m * PP + n] = valid ? acc[ni][e] : -1e30f;
        }
    }
    __syncthreads();

    // ---------------- phase B: softmax + split P -----------------------------
#pragma unroll
    for (int rr = 0; rr < 4; rr++) {
        const int q = warp * 4 + rr;
        float v[5];
        float mx = -1e30f;
#pragma unroll
        for (int s = 0; s < 5; s++) {
            v[s] = Ps[q * PP + lane + 32 * s];
            mx = fmaxf(mx, v[s]);
        }
#pragma unroll
        for (int off = 16; off; off >>= 1)
            mx = fmaxf(mx, __shfl_xor_sync(0xFFFFFFFFu, mx, off));
        float sum = 0.f;
#pragma unroll
        for (int s = 0; s < 5; s++) {
            v[s] = __expf(v[s] - mx);
            sum += v[s];
        }
#pragma unroll
        for (int off = 16; off; off >>= 1)
            sum += __shfl_xor_sync(0xFFFFFFFFu, sum, off);
        const float inv = 1.f / sum;
#pragma unroll
        for (int s = 0; s < 5; s++) {
            const float p = v[s] * inv;
            const __nv_bfloat16 ph = __float2bfloat16(p);
            const __nv_bfloat16 pl = __float2bfloat16(p - __bfloat162float(ph));
            Ph[q * PP + lane + 32 * s] = ph;
            Pl[q * PP + lane + 32 * s] = pl;
        }
    }

    // ---------------- phase C: O = P V ---------------------------------------
    const int wn2 = (warp & 3) * 16;       // 4 warp-groups along D (64)
    const size_t vbase = (size_t)b * DIM * T_SZ;

    for (int dc = 0; dc < DIM / DC; dc++) {
        const int d0 = dc * DC;
        __syncthreads();   // Ps dead / previous Vt consumed
#pragma unroll
        for (int it = 0; it < 5; it++) {
            const int idx = tid + it * 256;
            const int r = idx / 20;            // d-row 0..63
            const int c8 = (idx % 20) * 8;     // key col 0..152
            int j = jbase + c8;
            if (j < 0) j = 0;                  // clamped; p=0 there
            const size_t off = vbase + (size_t)(d0 + r) * T_SZ + j;
            *(uint4*)&Vth[r * PP + c8] = *(const uint4*)(g_vth + off);
            *(uint4*)&Vtl[r * PP + c8] = *(const uint4*)(g_vtl + off);
        }
        __syncthreads();

        float oacc[2][4] = {};
#pragma unroll
        for (int ks = 0; ks < NK / 16; ks++) {
            const int k = ks * 16;
            uint32_t ph_[4], pl_[4];
            {
                const int r0 = wm + g;
                ph_[0] = *(const uint32_t*)&Ph[r0 * PP + k + tig * 2];
                ph_[1] = *(const uint32_t*)&Ph[(r0 + 8) * PP + k + tig * 2];
                ph_[2] = *(const uint32_t*)&Ph[r0 * PP + k + 8 + tig * 2];
                ph_[3] = *(const uint32_t*)&Ph[(r0 + 8) * PP + k + 8 + tig * 2];
                pl_[0] = *(const uint32_t*)&Pl[r0 * PP + k + tig * 2];
                pl_[1] = *(const uint32_t*)&Pl[(r0 + 8) * PP + k + tig * 2];
                pl_[2] = *(const uint32_t*)&Pl[r0 * PP + k + 8 + tig * 2];
                pl_[3] = *(const uint32_t*)&Pl[(r0 + 8) * PP + k + 8 + tig * 2];
            }
#pragma unroll
            for (int ni = 0; ni < 2; ni++) {
                const int n0 = wn2 + ni * 8 + g;
                const uint32_t vh0 = *(const uint32_t*)&Vth[n0 * PP + k + tig * 2];
                const uint32_t vh1 = *(const uint32_t*)&Vth[n0 * PP + k + 8 + tig * 2];
                const uint32_t vl0 = *(const uint32_t*)&Vtl[n0 * PP + k + tig * 2];
                const uint32_t vl1 = *(const uint32_t*)&Vtl[n0 * PP + k + 8 + tig * 2];
                mma16816(oacc[ni], ph_, vh0, vh1);
                mma16816(oacc[ni], ph_, vl0, vl1);
                mma16816(oacc[ni], pl_, vh0, vh1);
            }
        }

        // store O chunk
#pragma unroll
        for (int ni = 0; ni < 2; ni++) {
            const int m0 = wm + g;
            const int col = d0 + wn2 + ni * 8 + tig * 2;
            const size_t row = (size_t)b * T_SZ + i0 + m0;
            float2 v0 = {oacc[ni][0], oacc[ni][1]};
            float2 v1 = {oacc[ni][2], oacc[ni][3]};
            *(float2*)&out[row * DIM + col]       = v0;
            *(float2*)&out[(row + 8) * DIM + col] = v1;
        }
    }
}

// ---------------- launch -----------------------------------------------------
extern "C" void kernel_launch(void* const* d_in, const int* in_sizes, int n_in,
                              void* d_out, int out_size)
{
    const float* x    = (const float*)d_in[0];
    const float* Wqkv = (const float*)d_in[1];
    const float* bqkv = (const float*)d_in[2];
    float* out = (float*)d_out;

    cudaFuncSetAttribute(attn_mma,
                         cudaFuncAttributeMaxDynamicSharedMemorySize, AT_SMEM);
    cudaFuncSetAttribute(qkv_mma,
                         cudaFuncAttributeMaxDynamicSharedMemorySize, GSMEM_BYTES);

    __nv_bfloat16 *ah, *al, *wh, *wl;
    cudaGetSymbolAddress((void**)&ah, g_Ah);
    cudaGetSymbolAddress((void**)&al, g_Al);
    cudaGetSymbolAddress((void**)&wh, g_Wh);
    cudaGetSymbolAddress((void**)&wl, g_Wl);

    {
        int n4 = (M_TOT * DIM) / 4;
        cvt_split<<<(n4 + 255) / 256, 256>>>(x, ah, al, n4);
    }
    {
        int n4 = (E3 * DIM) / 4;
        cvt_split<<<(n4 + 255) / 256, 256>>>(Wqkv, wh, wl, n4);
    }

    dim3 ggrid(E3 / GBN, M_TOT / GBM);       // (12, 128)
    qkv_mma<<<ggrid, GTHREADS, GSMEM_BYTES>>>(bqkv);

    dim3 agrid(T_SZ / QT, B_SZ);             // (128, 4)
    attn_mma<<<agrid, 256, AT_SMEM>>>(out);
}

// round 9
// speedup vs baseline: 1.8643x; 1.0410x over previous
#include <cuda_runtime.h>
#include <cuda_bf16.h>
#include <cstdint>

#define B_SZ 4
#define T_SZ 4096
#define DIM 512
#define E3 1536
#define HIST 128
#define M_TOT (B_SZ * T_SZ)   // 16384
#define QSCALE 0.04419417382415922f   // 1/sqrt(512)

// ---------------- device scratch (allocation-free rule) ----------------------
__device__ __align__(16) __nv_bfloat16 g_Ah[(size_t)M_TOT * DIM];
__device__ __align__(16) __nv_bfloat16 g_Al[(size_t)M_TOT * DIM];
__device__ __align__(16) __nv_bfloat16 g_Wh[(size_t)E3 * DIM];
__device__ __align__(16) __nv_bfloat16 g_Wl[(size_t)E3 * DIM];

__device__ __align__(16) __nv_bfloat16 g_qh[(size_t)M_TOT * DIM];
__device__ __align__(16) __nv_bfloat16 g_ql[(size_t)M_TOT * DIM];
__device__ __align__(16) __nv_bfloat16 g_kh[(size_t)M_TOT * DIM];
__device__ __align__(16) __nv_bfloat16 g_kl[(size_t)M_TOT * DIM];
__device__ __align__(16) __nv_bfloat16 g_vth[(size_t)B_SZ * DIM * T_SZ];
__device__ __align__(16) __nv_bfloat16 g_vtl[(size_t)B_SZ * DIM * T_SZ];

// ---------------- helpers ----------------------------------------------------
__device__ __forceinline__ void split2(float v0, float v1, uint32_t& h, uint32_t& l)
{
    __nv_bfloat16 h0 = __float2bfloat16(v0);
    __nv_bfloat16 h1 = __float2bfloat16(v1);
    __nv_bfloat16 l0 = __float2bfloat16(v0 - __bfloat162float(h0));
    __nv_bfloat16 l1 = __float2bfloat16(v1 - __bfloat162float(h1));
    h = ((uint32_t)__bfloat16_as_ushort(h1) << 16) | __bfloat16_as_ushort(h0);
    l = ((uint32_t)__bfloat16_as_ushort(l1) << 16) | __bfloat16_as_ushort(l0);
}

__device__ __forceinline__ void mma16816(float* c, const uint32_t* a, uint32_t b0, uint32_t b1)
{
    asm volatile(
        "mma.sync.aligned.m16n8k16.row.col.f32.bf16.bf16.f32 "
        "{%0,%1,%2,%3}, {%4,%5,%6,%7}, {%8,%9}, {%0,%1,%2,%3};\n"
        : "+f"(c[0]), "+f"(c[1]), "+f"(c[2]), "+f"(c[3])
        : "r"(a[0]), "r"(a[1]), "r"(a[2]), "r"(a[3]), "r"(b0), "r"(b1));
}

__device__ __forceinline__ uint32_t sptr(const void* p)
{
    return (uint32_t)__cvta_generic_to_shared(p);
}

__device__ __forceinline__ void ldsm4(uint32_t* r, uint32_t addr)
{
    asm volatile("ldmatrix.sync.aligned.m8n8.x4.shared.b16 {%0,%1,%2,%3}, [%4];"
        : "=r"(r[0]), "=r"(r[1]), "=r"(r[2]), "=r"(r[3]) : "r"(addr));
}

__device__ __forceinline__ void ldsm2(uint32_t* r, uint32_t addr)
{
    asm volatile("ldmatrix.sync.aligned.m8n8.x2.shared.b16 {%0,%1}, [%2];"
        : "=r"(r[0]), "=r"(r[1]) : "r"(addr));
}

__device__ __forceinline__ void cpasync16(uint32_t dst, const void* src)
{
    asm volatile("cp.async.cg.shared.global [%0], [%1], 16;" :: "r"(dst), "l"(src));
}

// ---------------- fp32 -> (hi, lo) bf16 split --------------------------------
__global__ __launch_bounds__(256) void cvt_split(
    const float* __restrict__ src,
    __nv_bfloat16* __restrict__ hi, __nv_bfloat16* __restrict__ lo, int n4)
{
    int i = blockIdx.x * 256 + threadIdx.x;
    if (i >= n4) return;
    float4 v = ((const float4*)src)[i];
    uint32_t h0, l0, h1, l1;
    split2(v.x, v.y, h0, l0);
    split2(v.z, v.w, h1, l1);
    uint2 h = {h0, h1}, l = {l0, l1};
    ((uint2*)hi)[i] = h;
    ((uint2*)lo)[i] = l;
}

// ---------------- QKV GEMM: 512 threads, GBK=64, cp.async x2, ldmatrix -------
#define GBM 128
#define GBN 128
#define GBK 64
#define GTHREADS 512
#define APITCH 72
#define MAT_BF (GBM * APITCH)             // 9216 bf16 per matrix
#define STAGE_BF (4 * MAT_BF)
#define GSMEM_BYTES (2 * STAGE_BF * 2)    // 147456

__device__ __forceinline__ void gemm_load_stage(
    __nv_bfloat16* stage, const __nv_bfloat16* Ah, const __nv_bfloat16* Al,
    const __nv_bfloat16* Bh, const __nv_bfloat16* Bl, int k0, int tid)
{
    const __nv_bfloat16* srcs[4] = {Ah, Al, Bh, Bl};
#pragma unroll
    for (int m = 0; m < 4; m++) {
        __nv_bfloat16* mb = stage + m * MAT_BF;
        const __nv_bfloat16* gb = srcs[m];
#pragma unroll
        for (int it = 0; it < 2; it++) {
            const int idx = tid + it * GTHREADS;
            const int r = idx >> 3;
            const int c = (idx & 7) * 8;
            cpasync16(sptr(mb + r * APITCH + c), gb + (size_t)r * DIM + k0 + c);
        }
    }
}

__global__ __launch_bounds__(GTHREADS) void qkv_mma(const float* __restrict__ bias)
{
    extern __shared__ __align__(16) __nv_bfloat16 gsm[];

    const int tid  = threadIdx.x;
    const int warp = tid >> 5, lane = tid & 31;
    const int wm = (warp >> 2) * 32;
    const int wn = (warp & 3) * 32;
    const int g  = lane >> 2, tig = lane & 3;

    const int bm = blockIdx.y * GBM;
    const int bn = blockIdx.x * GBN;

    const __nv_bfloat16* Ah = g_Ah + (size_t)bm * DIM;
    const __nv_bfloat16* Al = g_Al + (size_t)bm * DIM;
    const __nv_bfloat16* Bh = g_Wh + (size_t)bn * DIM;
    const __nv_bfloat16* Bl = g_Wl + (size_t)bn * DIM;

    float acc[2][4][4] = {};

    const int arow = (lane & 15);
    const int acol = (lane >> 4) << 3;
    const int brow = ((lane >> 4) << 3) + (lane & 7);
    const int bcol = ((lane >> 3) & 1) << 3;

    gemm_load_stage(gsm, Ah, Al, Bh, Bl, 0, tid);
    asm volatile("cp.async.commit_group;");

    const int NCH = DIM / GBK;   // 8
    for (int ch = 0; ch < NCH; ch++) {
        __nv_bfloat16* stg = gsm + (ch & 1) * STAGE_BF;
        if (ch + 1 < NCH) {
            gemm_load_stage(gsm + ((ch + 1) & 1) * STAGE_BF, Ah, Al, Bh, Bl,
                            (ch + 1) * GBK, tid);
            asm volatile("cp.async.commit_group;");
            asm volatile("cp.async.wait_group 1;");
        } else {
            asm volatile("cp.async.wait_group 0;");
        }
        __syncthreads();

        __nv_bfloat16* sAh = stg;
        __nv_bfloat16* sAl = stg + MAT_BF;
        __nv_bfloat16* sBh = stg + 2 * MAT_BF;
        __nv_bfloat16* sBl = stg + 3 * MAT_BF;

#pragma unroll
        for (int ks = 0; ks < GBK / 16; ks++) {
            const int k = ks * 16;
            uint32_t ah[2][4], al[2][4];
#pragma unroll
            for (int mi = 0; mi < 2; mi++) {
                const int r = wm + mi * 16 + arow;
                ldsm4(ah[mi], sptr(sAh + r * APITCH + k + acol));
                ldsm4(al[mi], sptr(sAl + r * APITCH + k + acol));
            }
#pragma unroll
            for (int np = 0; np < 2; np++) {
                const int n0 = wn + np * 16 + brow;
                uint32_t bh[4], bl[4];
                ldsm4(bh, sptr(sBh + n0 * APITCH + k + bcol));
                ldsm4(bl, sptr(sBl + n0 * APITCH + k + bcol));
#pragma unroll
                for (int mi = 0; mi < 2; mi++) {
                    float* c0 = acc[mi][2 * np];
                    float* c1 = acc[mi][2 * np + 1];
                    mma16816(c0, ah[mi], bh[0], bh[1]);
                    mma16816(c0, ah[mi], bl[0], bl[1]);
                    mma16816(c0, al[mi], bh[0], bh[1]);
                    mma16816(c1, ah[mi], bh[2], bh[3]);
                    mma16816(c1, ah[mi], bl[2], bl[3]);
                    mma16816(c1, al[mi], bh[2], bh[3]);
                }
            }
        }
        __syncthreads();
    }

    const int sec = bn >> 9;            // 0=q, 1=k, 2=v
#pragma unroll
    for (int mi = 0; mi < 2; mi++) {
#pragma unroll
        for (int ni = 0; ni < 4; ni++) {
            const int m0 = bm + wm + mi * 16 + g;
            const int cc = bn + wn + ni * 8 + tig * 2;
            const int lc = cc & 511;
            const float bb0 = bias[cc], bb1 = bias[cc + 1];
            float v00 = acc[mi][ni][0] + bb0, v01 = acc[mi][ni][1] + bb1;
            float v10 = acc[mi][ni][2] + bb0, v11 = acc[mi][ni][3] + bb1;
            if (sec == 0) { v00 *= QSCALE; v01 *= QSCALE; v10 *= QSCALE; v11 *= QSCALE; }
            uint32_t h0, l0, h1, l1;
            split2(v00, v01, h0, l0);
            split2(v10, v11, h1, l1);
            if (sec == 0) {
                *(uint32_t*)&g_qh[(size_t)m0 * DIM + lc]       = h0;
                *(uint32_t*)&g_ql[(size_t)m0 * DIM + lc]       = l0;
                *(uint32_t*)&g_qh[(size_t)(m0 + 8) * DIM + lc] = h1;
                *(uint32_t*)&g_ql[(size_t)(m0 + 8) * DIM + lc] = l1;
            } else if (sec == 1) {
                *(uint32_t*)&g_kh[(size_t)m0 * DIM + lc]       = h0;
                *(uint32_t*)&g_kl[(size_t)m0 * DIM + lc]       = l0;
                *(uint32_t*)&g_kh[(size_t)(m0 + 8) * DIM + lc] = h1;
                *(uint32_t*)&g_kl[(size_t)(m0 + 8) * DIM + lc] = l1;
            } else {
                const int b = m0 >> 12, t = m0 & 4095;
                const size_t base = (size_t)b * DIM * T_SZ;
                g_vth[base + (size_t)lc * T_SZ + t]           = __ushort_as_bfloat16((unsigned short)(h0 & 0xFFFF));
                g_vth[base + (size_t)(lc + 1) * T_SZ + t]     = __ushort_as_bfloat16((unsigned short)(h0 >> 16));
                g_vtl[base + (size_t)lc * T_SZ + t]           = __ushort_as_bfloat16((unsigned short)(l0 & 0xFFFF));
                g_vtl[base + (size_t)(lc + 1) * T_SZ + t]     = __ushort_as_bfloat16((unsigned short)(l0 >> 16));
                g_vth[base + (size_t)lc * T_SZ + t + 8]       = __ushort_as_bfloat16((unsigned short)(h1 & 0xFFFF));
                g_vth[base + (size_t)(lc + 1) * T_SZ + t + 8] = __ushort_as_bfloat16((unsigned short)(h1 >> 16));
                g_vtl[base + (size_t)lc * T_SZ + t + 8]       = __ushort_as_bfloat16((unsigned short)(l1 & 0xFFFF));
                g_vtl[base + (size_t)(lc + 1) * T_SZ + t + 8] = __ushort_as_bfloat16((unsigned short)(l1 >> 16));
            }
        }
    }
}

// ---------------- Banded attention: QT=32, ldmatrix + cp.async ---------------
#define QT 32
#define NK 160
#define DC 64
#define KP 72
#define PP 168

#define AT_SMEM 76800

__global__ __launch_bounds__(256, 2) void attn_mma(float* __restrict__ out)
{
    extern __shared__ char sm[];
    __nv_bfloat16* Qh = (__nv_bfloat16*)sm;
    __nv_bfloat16* Ql = (__nv_bfloat16*)(sm + 4608);
    __nv_bfloat16* Kh = (__nv_bfloat16*)(sm + 9216);
    __nv_bfloat16* Kl = (__nv_bfloat16*)(sm + 32256);
    float*         Ps = (float*)sm;
    __nv_bfloat16* Vth = (__nv_bfloat16*)sm;
    __nv_bfloat16* Vtl = (__nv_bfloat16*)(sm + 21504);
    __nv_bfloat16* Ph = (__nv_bfloat16*)(sm + 55296);
    __nv_bfloat16* Pl = (__nv_bfloat16*)(sm + 66048);

    const int b   = blockIdx.y;
    const int i0  = blockIdx.x * QT;
    const int tid = threadIdx.x;
    const int warp = tid >> 5, lane = tid & 31;
    const int g = lane >> 2, tig = lane & 3;
    const int jbase = i0 - HIST;

    // ldmatrix lane addressing
    const int arow = lane & 15;
    const int acol = (lane >> 4) << 3;
    const int brow = ((lane >> 4) << 3) + (lane & 7);
    const int bcol = ((lane >> 3) & 1) << 3;
    const int l15  = lane & 15;
    const int b2row = l15 & 7;
    const int b2col = ((l15 >> 3) & 1) << 3;

    // ---------------- phase A: S = Q K^T -------------------------------------
    const int wm = (warp >> 2) * 16;       // 2 warp-groups along M (32)
    const int wn = (warp & 3) * 40;        // 4 warp-groups along N (160)
    float acc[5][4] = {};

    for (int dc = 0; dc < DIM / DC; dc++) {
        const int d0 = dc * DC;
        __syncthreads();
        {
            const int r = tid >> 3, c8 = (tid & 7) * 8;
            const size_t off = (size_t)(b * T_SZ + i0 + r) * DIM + d0 + c8;
            cpasync16(sptr(&Qh[r * KP + c8]), g_qh + off);
            cpasync16(sptr(&Ql[r * KP + c8]), g_ql + off);
        }
#pragma unroll
        for (int it = 0; it < 5; it++) {
            const int idx = tid + it * 256;
            const int r = idx >> 3, c8 = (idx & 7) * 8;
            const int j = jbase + r;
            const int jc = j < 0 ? 0 : j;
            const size_t off = (size_t)(b * T_SZ + jc) * DIM + d0 + c8;
            cpasync16(sptr(&Kh[r * KP + c8]), g_kh + off);
            cpasync16(sptr(&Kl[r * KP + c8]), g_kl + off);
        }
        asm volatile("cp.async.commit_group;");
        asm volatile("cp.async.wait_group 0;");
        __syncthreads();

#pragma unroll
        for (int ks = 0; ks < DC / 16; ks++) {
            const int k = ks * 16;
            uint32_t ah[4], al[4];
            ldsm4(ah, sptr(&Qh[(wm + arow) * KP + k + acol]));
            ldsm4(al, sptr(&Ql[(wm + arow) * KP + k + acol]));
            uint32_t bh[10], bl[10];
            ldsm4(bh,     sptr(&Kh[(wn +      brow) * KP + k + bcol]));
            ldsm4(bh + 4, sptr(&Kh[(wn + 16 + brow) * KP + k + bcol]));
            ldsm2(bh + 8, sptr(&Kh[(wn + 32 + b2row) * KP + k + b2col]));
            ldsm4(bl,     sptr(&Kl[(wn +      brow) * KP + k + bcol]));
            ldsm4(bl + 4, sptr(&Kl[(wn + 16 + brow) * KP + k + bcol]));
            ldsm2(bl + 8, sptr(&Kl[(wn + 32 + b2row) * KP + k + b2col]));
#pragma unroll
            for (int ni = 0; ni < 5; ni++) {
                mma16816(acc[ni], ah, bh[2 * ni], bh[2 * ni + 1]);
                mma16816(acc[ni], ah, bl[2 * ni], bl[2 * ni + 1]);
                mma16816(acc[ni], al, bh[2 * ni], bh[2 * ni + 1]);
            }
        }
    }
    __syncthreads();

    // masked store of S to Ps
#pragma unroll
    for (int ni = 0; ni < 5; ni++) {
        const int m0 = wm + g;
        const int n0 = wn + ni * 8 + tig * 2;
#pragma unroll
        for (int e = 0; e < 4; e++) {
            const int m = m0 + (e >> 1) * 8;
            const int n = n0 + (e & 1);
            const bool valid = (n >= m) && (n <= m + HIST) && (jbase + n >= 0);
            Ps[m * PP + n] = valid ? acc[ni][e] : -1e30f;
        }
    }
    __syncthreads();

    // ---------------- phase B: softmax + split P -----------------------------
#pragma unroll
    for (int rr = 0; rr < 4; rr++) {
        const int q = warp * 4 + rr;
        float v[5];
        float mx = -1e30f;
#pragma unroll
        for (int s = 0; s < 5; s++) {
            v[s] = Ps[q * PP + lane + 32 * s];
            mx = fmaxf(mx, v[s]);
        }
#pragma unroll
        for (int off = 16; off; off >>= 1)
            mx = fmaxf(mx, __shfl_xor_sync(0xFFFFFFFFu, mx, off));
        float sum = 0.f;
#pragma unroll
        for (int s = 0; s < 5; s++) {
            v[s] = __expf(v[s] - mx);
            sum += v[s];
        }
#pragma unroll
        for (int off = 16; off; off >>= 1)
            sum += __shfl_xor_sync(0xFFFFFFFFu, sum, off);
        const float inv = 1.f / sum;
#pragma unroll
        for (int s = 0; s < 5; s++) {
            const float p = v[s] * inv;
            const __nv_bfloat16 ph = __float2bfloat16(p);
            const __nv_bfloat16 pl = __float2bfloat16(p - __bfloat162float(ph));
            Ph[q * PP + lane + 32 * s] = ph;
            Pl[q * PP + lane + 32 * s] = pl;
        }
    }

    // ---------------- phase C: O = P V ---------------------------------------
    const int wn2 = (warp & 3) * 16;       // 4 warp-groups along D (64)
    const size_t vbase = (size_t)b * DIM * T_SZ;

    for (int dc = 0; dc < DIM / DC; dc++) {
        const int d0 = dc * DC;
        __syncthreads();   // Ps dead / previous Vt consumed
#pragma unroll
        for (int it = 0; it < 5; it++) {
            const int idx = tid + it * 256;
            const int r = idx / 20;            // d-row 0..63
            const int c8 = (idx % 20) * 8;     // key col 0..152
            int j = jbase + c8;
            if (j < 0) j = 0;                  // clamped; p=0 there
            const size_t off = vbase + (size_t)(d0 + r) * T_SZ + j;
            cpasync16(sptr(&Vth[r * PP + c8]), g_vth + off);
            cpasync16(sptr(&Vtl[r * PP + c8]), g_vtl + off);
        }
        asm volatile("cp.async.commit_group;");
        asm volatile("cp.async.wait_group 0;");
        __syncthreads();

        float oacc[2][4] = {};
#pragma unroll
        for (int ks = 0; ks < NK / 16; ks++) {
            const int k = ks * 16;
            uint32_t ph_[4], pl_[4], vh[4], vl[4];
            ldsm4(ph_, sptr(&Ph[(wm + arow) * PP + k + acol]));
            ldsm4(pl_, sptr(&Pl[(wm + arow) * PP + k + acol]));
            ldsm4(vh,  sptr(&Vth[(wn2 + brow) * PP + k + bcol]));
            ldsm4(vl,  sptr(&Vtl[(wn2 + brow) * PP + k + bcol]));
            mma16816(oacc[0], ph_, vh[0], vh[1]);
            mma16816(oacc[0], ph_, vl[0], vl[1]);
            mma16816(oacc[0], pl_, vh[0], vh[1]);
            mma16816(oacc[1], ph_, vh[2], vh[3]);
            mma16816(oacc[1], ph_, vl[2], vl[3]);
            mma16816(oacc[1], pl_, vh[2], vh[3]);
        }

        // store O chunk
#pragma unroll
        for (int ni = 0; ni < 2; ni++) {
            const int m0 = wm + g;
            const int col = d0 + wn2 + ni * 8 + tig * 2;
            const size_t row = (size_t)b * T_SZ + i0 + m0;
            float2 v0 = {oacc[ni][0], oacc[ni][1]};
            float2 v1 = {oacc[ni][2], oacc[ni][3]};
            *(float2*)&out[row * DIM + col]       = v0;
            *(float2*)&out[(row + 8) * DIM + col] = v1;
        }
    }
}

// ---------------- launch -----------------------------------------------------
extern "C" void kernel_launch(void* const* d_in, const int* in_sizes, int n_in,
                              void* d_out, int out_size)
{
    const float* x    = (const float*)d_in[0];
    const float* Wqkv = (const float*)d_in[1];
    const float* bqkv = (const float*)d_in[2];
    float* out = (float*)d_out;

    cudaFuncSetAttribute(attn_mma,
                         cudaFuncAttributeMaxDynamicSharedMemorySize, AT_SMEM);
    cudaFuncSetAttribute(qkv_mma,
                         cudaFuncAttributeMaxDynamicSharedMemorySize, GSMEM_BYTES);

    __nv_bfloat16 *ah, *al, *wh, *wl;
    cudaGetSymbolAddress((void**)&ah, g_Ah);
    cudaGetSymbolAddress((void**)&al, g_Al);
    cudaGetSymbolAddress((void**)&wh, g_Wh);
    cudaGetSymbolAddress((void**)&wl, g_Wl);

    {
        int n4 = (M_TOT * DIM) / 4;
        cvt_split<<<(n4 + 255) / 256, 256>>>(x, ah, al, n4);
    }
    {
        int n4 = (E3 * DIM) / 4;
        cvt_split<<<(n4 + 255) / 256, 256>>>(Wqkv, wh, wl, n4);
    }

    dim3 ggrid(E3 / GBN, M_TOT / GBM);       // (12, 128)
    qkv_mma<<<ggrid, GTHREADS, GSMEM_BYTES>>>(bqkv);

    dim3 agrid(T_SZ / QT, B_SZ);             // (128, 4)
    attn_mma<<<agrid, 256, AT_SMEM>>>(out);
}

// round 10
// speedup vs baseline: 4.1662x; 2.2347x over previous
#include <cuda_runtime.h>
#include <cuda_fp16.h>
#include <cstdint>

#define B_SZ 4
#define T_SZ 4096
#define DIM 512
#define E3 1536
#define HIST 128
#define M_TOT (B_SZ * T_SZ)   // 16384
#define QSCALE 0.04419417382415922f   // 1/sqrt(512)

// ---------------- device scratch (allocation-free rule) ----------------------
__device__ __align__(16) __half g_A[(size_t)M_TOT * DIM];
__device__ __align__(16) __half g_W[(size_t)E3 * DIM];
__device__ __align__(16) __half g_q[(size_t)M_TOT * DIM];
__device__ __align__(16) __half g_k[(size_t)M_TOT * DIM];
__device__ __align__(16) __half g_vt[(size_t)B_SZ * DIM * T_SZ];

// ---------------- helpers ----------------------------------------------------
__device__ __forceinline__ void mma16816(float* c, const uint32_t* a, uint32_t b0, uint32_t b1)
{
    asm volatile(
        "mma.sync.aligned.m16n8k16.row.col.f32.f16.f16.f32 "
        "{%0,%1,%2,%3}, {%4,%5,%6,%7}, {%8,%9}, {%0,%1,%2,%3};\n"
        : "+f"(c[0]), "+f"(c[1]), "+f"(c[2]), "+f"(c[3])
        : "r"(a[0]), "r"(a[1]), "r"(a[2]), "r"(a[3]), "r"(b0), "r"(b1));
}

__device__ __forceinline__ uint32_t sptr(const void* p)
{
    return (uint32_t)__cvta_generic_to_shared(p);
}

__device__ __forceinline__ void ldsm4(uint32_t* r, uint32_t addr)
{
    asm volatile("ldmatrix.sync.aligned.m8n8.x4.shared.b16 {%0,%1,%2,%3}, [%4];"
        : "=r"(r[0]), "=r"(r[1]), "=r"(r[2]), "=r"(r[3]) : "r"(addr));
}

__device__ __forceinline__ void ldsm2(uint32_t* r, uint32_t addr)
{
    asm volatile("ldmatrix.sync.aligned.m8n8.x2.shared.b16 {%0,%1}, [%2];"
        : "=r"(r[0]), "=r"(r[1]) : "r"(addr));
}

__device__ __forceinline__ void cpasync16(uint32_t dst, const void* src)
{
    asm volatile("cp.async.cg.shared.global [%0], [%1], 16;" :: "r"(dst), "l"(src));
}

__device__ __forceinline__ uint32_t packh(float a, float b)
{
    __half2 h = __floats2half2_rn(a, b);
    return *(uint32_t*)&h;
}

// ---------------- fp32 -> fp16 convert ---------------------------------------
__global__ __launch_bounds__(256) void cvt16(
    const float* __restrict__ src, __half* __restrict__ dst, int n4)
{
    int i = blockIdx.x * 256 + threadIdx.x;
    if (i >= n4) return;
    float4 v = ((const float4*)src)[i];
    uint2 u;
    u.x = packh(v.x, v.y);
    u.y = packh(v.z, v.w);
    ((uint2*)dst)[i] = u;
}

// ---------------- QKV GEMM: fp16 single-product, cp.async x2, ldmatrix -------
#define GBM 128
#define GBN 128
#define GBK 64
#define GTHREADS 512
#define APITCH 72
#define MAT_F (GBM * APITCH)              // 9216 halves per matrix
#define STAGE_F (2 * MAT_F)               // A, B
#define GSMEM_BYTES (2 * STAGE_F * 2)     // 73728

__device__ __forceinline__ void gemm_load_stage(
    __half* stage, const __half* A, const __half* B, int k0, int tid)
{
    const __half* srcs[2] = {A, B};
#pragma unroll
    for (int m = 0; m < 2; m++) {
        __half* mb = stage + m * MAT_F;
        const __half* gb = srcs[m];
#pragma unroll
        for (int it = 0; it < 2; it++) {
            const int idx = tid + it * GTHREADS;   // 0..1023
            const int r = idx >> 3;
            const int c = (idx & 7) * 8;
            cpasync16(sptr(mb + r * APITCH + c), gb + (size_t)r * DIM + k0 + c);
        }
    }
}

__global__ __launch_bounds__(GTHREADS) void qkv_mma(const float* __restrict__ bias)
{
    extern __shared__ __align__(16) __half gsm[];

    const int tid  = threadIdx.x;
    const int warp = tid >> 5, lane = tid & 31;
    const int wm = (warp >> 2) * 32;
    const int wn = (warp & 3) * 32;
    const int g  = lane >> 2, tig = lane & 3;

    const int bm = blockIdx.y * GBM;
    const int bn = blockIdx.x * GBN;

    const __half* A = g_A + (size_t)bm * DIM;
    const __half* B = g_W + (size_t)bn * DIM;

    float acc[2][4][4] = {};

    const int arow = (lane & 15);
    const int acol = (lane >> 4) << 3;
    const int brow = ((lane >> 4) << 3) + (lane & 7);
    const int bcol = ((lane >> 3) & 1) << 3;

    gemm_load_stage(gsm, A, B, 0, tid);
    asm volatile("cp.async.commit_group;");

    const int NCH = DIM / GBK;   // 8
    for (int ch = 0; ch < NCH; ch++) {
        __half* stg = gsm + (ch & 1) * STAGE_F;
        if (ch + 1 < NCH) {
            gemm_load_stage(gsm + ((ch + 1) & 1) * STAGE_F, A, B, (ch + 1) * GBK, tid);
            asm volatile("cp.async.commit_group;");
            asm volatile("cp.async.wait_group 1;");
        } else {
            asm volatile("cp.async.wait_group 0;");
        }
        __syncthreads();

        __half* sA = stg;
        __half* sB = stg + MAT_F;

#pragma unroll
        for (int ks = 0; ks < GBK / 16; ks++) {
            const int k = ks * 16;
            uint32_t a[2][4];
#pragma unroll
            for (int mi = 0; mi < 2; mi++)
                ldsm4(a[mi], sptr(sA + (wm + mi * 16 + arow) * APITCH + k + acol));
#pragma unroll
            for (int np = 0; np < 2; np++) {
                uint32_t b[4];
                ldsm4(b, sptr(sB + (wn + np * 16 + brow) * APITCH + k + bcol));
#pragma unroll
                for (int mi = 0; mi < 2; mi++) {
                    mma16816(acc[mi][2 * np],     a[mi], b[0], b[1]);
                    mma16816(acc[mi][2 * np + 1], a[mi], b[2], b[3]);
                }
            }
        }
        __syncthreads();
    }

    // epilogue: bias, route to q (scaled) / k / v-transposed fp16 stores
    const int sec = bn >> 9;            // 0=q, 1=k, 2=v
#pragma unroll
    for (int mi = 0; mi < 2; mi++) {
#pragma unroll
        for (int ni = 0; ni < 4; ni++) {
            const int m0 = bm + wm + mi * 16 + g;
            const int cc = bn + wn + ni * 8 + tig * 2;
            const int lc = cc & 511;
            const float bb0 = bias[cc], bb1 = bias[cc + 1];
            float v00 = acc[mi][ni][0] + bb0, v01 = acc[mi][ni][1] + bb1;
            float v10 = acc[mi][ni][2] + bb0, v11 = acc[mi][ni][3] + bb1;
            if (sec == 0) { v00 *= QSCALE; v01 *= QSCALE; v10 *= QSCALE; v11 *= QSCALE; }
            const uint32_t p0 = packh(v00, v01);
            const uint32_t p1 = packh(v10, v11);
            if (sec == 0) {
                *(uint32_t*)&g_q[(size_t)m0 * DIM + lc]       = p0;
                *(uint32_t*)&g_q[(size_t)(m0 + 8) * DIM + lc] = p1;
            } else if (sec == 1) {
                *(uint32_t*)&g_k[(size_t)m0 * DIM + lc]       = p0;
                *(uint32_t*)&g_k[(size_t)(m0 + 8) * DIM + lc] = p1;
            } else {
                const int b = m0 >> 12, t = m0 & 4095;
                const size_t base = (size_t)b * DIM * T_SZ;
                g_vt[base + (size_t)lc * T_SZ + t]           = __float2half_rn(v00);
                g_vt[base + (size_t)(lc + 1) * T_SZ + t]     = __float2half_rn(v01);
                g_vt[base + (size_t)lc * T_SZ + t + 8]       = __float2half_rn(v10);
                g_vt[base + (size_t)(lc + 1) * T_SZ + t + 8] = __float2half_rn(v11);
            }
        }
    }
}

// ---------------- Banded attention: fp16 single-product ----------------------
#define QT 32
#define NK 160
#define DC 64
#define KP 72
#define PP 168

// smem (bytes):
//  region A (union):
//    phase A: Qs@0 (4608), Ks@4608 (23040)     -> 27648
//    phase B: Ps f32 @0 (32*168*4 = 21504)
//    phase C: Vt @0 (64*168*2 = 21504)
//  region B: Pw@27648 (10752)                   -> total 38400
#define AT_SMEM 38400

__global__ __launch_bounds__(256, 3) void attn_mma(float* __restrict__ out)
{
    extern __shared__ char sm[];
    __half* Qs = (__half*)sm;
    __half* Ks = (__half*)(sm + 4608);
    float*  Ps = (float*)sm;
    __half* Vt = (__half*)sm;
    __half* Pw = (__half*)(sm + 27648);

    const int b   = blockIdx.y;
    const int i0  = blockIdx.x * QT;
    const int tid = threadIdx.x;
    const int warp = tid >> 5, lane = tid & 31;
    const int g = lane >> 2, tig = lane & 3;
    const int jbase = i0 - HIST;

    const int arow = lane & 15;
    const int acol = (lane >> 4) << 3;
    const int brow = ((lane >> 4) << 3) + (lane & 7);
    const int bcol = ((lane >> 3) & 1) << 3;
    const int l15  = lane & 15;
    const int b2row = l15 & 7;
    const int b2col = ((l15 >> 3) & 1) << 3;

    // ---------------- phase A: S = Q K^T -------------------------------------
    const int wm = (warp >> 2) * 16;       // 2 warp-groups along M (32)
    const int wn = (warp & 3) * 40;        // 4 warp-groups along N (160)
    float acc[5][4] = {};

    for (int dc = 0; dc < DIM / DC; dc++) {
        const int d0 = dc * DC;
        __syncthreads();
        {
            const int r = tid >> 3, c8 = (tid & 7) * 8;
            const size_t off = (size_t)(b * T_SZ + i0 + r) * DIM + d0 + c8;
            cpasync16(sptr(&Qs[r * KP + c8]), g_q + off);
        }
#pragma unroll
        for (int it = 0; it < 5; it++) {
            const int idx = tid + it * 256;
            const int r = idx >> 3, c8 = (idx & 7) * 8;
            const int j = jbase + r;
            const int jc = j < 0 ? 0 : j;
            const size_t off = (size_t)(b * T_SZ + jc) * DIM + d0 + c8;
            cpasync16(sptr(&Ks[r * KP + c8]), g_k + off);
        }
        asm volatile("cp.async.commit_group;");
        asm volatile("cp.async.wait_group 0;");
        __syncthreads();

#pragma unroll
        for (int ks = 0; ks < DC / 16; ks++) {
            const int k = ks * 16;
            uint32_t a[4];
            ldsm4(a, sptr(&Qs[(wm + arow) * KP + k + acol]));
            uint32_t bb[10];
            ldsm4(bb,     sptr(&Ks[(wn +      brow) * KP + k + bcol]));
            ldsm4(bb + 4, sptr(&Ks[(wn + 16 + brow) * KP + k + bcol]));
            ldsm2(bb + 8, sptr(&Ks[(wn + 32 + b2row) * KP + k + b2col]));
#pragma unroll
            for (int ni = 0; ni < 5; ni++)
                mma16816(acc[ni], a, bb[2 * ni], bb[2 * ni + 1]);
        }
    }
    __syncthreads();

    // masked store of S to Ps
#pragma unroll
    for (int ni = 0; ni < 5; ni++) {
        const int m0 = wm + g;
        const int n0 = wn + ni * 8 + tig * 2;
#pragma unroll
        for (int e = 0; e < 4; e++) {
            const int m = m0 + (e >> 1) * 8;
            const int n = n0 + (e & 1);
            const bool valid = (n >= m) && (n <= m + HIST) && (jbase + n >= 0);
            Ps[m * PP + n] = valid ? acc[ni][e] : -1e30f;
        }
    }
    __syncthreads();

    // ---------------- phase B: softmax + fp16 P ------------------------------
#pragma unroll
    for (int rr = 0; rr < 4; rr++) {
        const int q = warp * 4 + rr;
        float v[5];
        float mx = -1e30f;
#pragma unroll
        for (int s = 0; s < 5; s++) {
            v[s] = Ps[q * PP + lane + 32 * s];
            mx = fmaxf(mx, v[s]);
        }
#pragma unroll
        for (int off = 16; off; off >>= 1)
            mx = fmaxf(mx, __shfl_xor_sync(0xFFFFFFFFu, mx, off));
        float sum = 0.f;
#pragma unroll
        for (int s = 0; s < 5; s++) {
            v[s] = __expf(v[s] - mx);
            sum += v[s];
        }
#pragma unroll
        for (int off = 16; off; off >>= 1)
            sum += __shfl_xor_sync(0xFFFFFFFFu, sum, off);
        const float inv = 1.f / sum;
#pragma unroll
        for (int s = 0; s < 5; s++)
            Pw[q * PP + lane + 32 * s] = __float2half_rn(v[s] * inv);
    }

    // ---------------- phase C: O = P V ---------------------------------------
    const int wn2 = (warp & 3) * 16;       // 4 warp-groups along D (64)
    const size_t vbase = (size_t)b * DIM * T_SZ;

    for (int dc = 0; dc < DIM / DC; dc++) {
        const int d0 = dc * DC;
        __syncthreads();   // Ps dead / previous Vt consumed
#pragma unroll
        for (int it = 0; it < 5; it++) {
            const int idx = tid + it * 256;
            const int r = idx / 20;            // d-row 0..63
            const int c8 = (idx % 20) * 8;     // key col 0..152
            int j = jbase + c8;
            if (j < 0) j = 0;                  // clamped; p=0 there
            const size_t off = vbase + (size_t)(d0 + r) * T_SZ + j;
            cpasync16(sptr(&Vt[r * PP + c8]), g_vt + off);
        }
        asm volatile("cp.async.commit_group;");
        asm volatile("cp.async.wait_group 0;");
        __syncthreads();

        float oacc[2][4] = {};
#pragma unroll
        for (int ks = 0; ks < NK / 16; ks++) {
            const int k = ks * 16;
            uint32_t pw[4], vv[4];
            ldsm4(pw, sptr(&Pw[(wm + arow) * PP + k + acol]));
            ldsm4(vv, sptr(&Vt[(wn2 + brow) * PP + k + bcol]));
            mma16816(oacc[0], pw, vv[0], vv[1]);
            mma16816(oacc[1], pw, vv[2], vv[3]);
        }

        // store O chunk
#pragma unroll
        for (int ni = 0; ni < 2; ni++) {
            const int m0 = wm + g;
            const int col = d0 + wn2 + ni * 8 + tig * 2;
            const size_t row = (size_t)b * T_SZ + i0 + m0;
            float2 v0 = {oacc[ni][0], oacc[ni][1]};
            float2 v1 = {oacc[ni][2], oacc[ni][3]};
            *(float2*)&out[row * DIM + col]       = v0;
            *(float2*)&out[(row + 8) * DIM + col] = v1;
        }
    }
}

// ---------------- launch -----------------------------------------------------
extern "C" void kernel_launch(void* const* d_in, const int* in_sizes, int n_in,
                              void* d_out, int out_size)
{
    const float* x    = (const float*)d_in[0];
    const float* Wqkv = (const float*)d_in[1];
    const float* bqkv = (const float*)d_in[2];
    float* out = (float*)d_out;

    cudaFuncSetAttribute(attn_mma,
                         cudaFuncAttributeMaxDynamicSharedMemorySize, AT_SMEM);
    cudaFuncSetAttribute(qkv_mma,
                         cudaFuncAttributeMaxDynamicSharedMemorySize, GSMEM_BYTES);

    __half *pa, *pw;
    cudaGetSymbolAddress((void**)&pa, g_A);
    cudaGetSymbolAddress((void**)&pw, g_W);

    {
        int n4 = (M_TOT * DIM) / 4;
        cvt16<<<(n4 + 255) / 256, 256>>>(x, pa, n4);
    }
    {
        int n4 = (E3 * DIM) / 4;
        cvt16<<<(n4 + 255) / 256, 256>>>(Wqkv, pw, n4);
    }

    dim3 ggrid(E3 / GBN, M_TOT / GBM);       // (12, 128)
    qkv_mma<<<ggrid, GTHREADS, GSMEM_BYTES>>>(bqkv);

    dim3 agrid(T_SZ / QT, B_SZ);             // (128, 4)
    attn_mma<<<agrid, 256, AT_SMEM>>>(out);
}